// round 1
// baseline (speedup 1.0000x reference)
#include <cuda_runtime.h>
#include <cuda_bf16.h>
#include <math.h>

// Problem constants (fixed shapes from reference)
#define BB   2
#define LQ   1024
#define LK   2048
#define HH   1024
#define NH   16
#define HD   64
#define EPS  1e-5f

// -------------------- scratch (device globals, no allocation) --------------------
__device__ float g_Q[BB * LQ * HH];     // 8 MB
__device__ float g_K[BB * LK * HH];     // 16 MB
__device__ float g_V[BB * LK * HH];     // 16 MB
__device__ float g_ctx[BB * LQ * HH];   // 8 MB
__device__ float g_x[BB * LQ * HH];     // 8 MB

// -------------------- GEMM: C[M,N] = A[M,K] @ W[N,K]^T + bias (+residual) -------
// Both A and W are K-contiguous (NT gemm). 64x64 block tile, BK=16, 256 threads,
// 4x4 register micro-tile per thread.
__global__ __launch_bounds__(256) void gemm_nt_bias(
    const float* __restrict__ A, const float* __restrict__ W,
    const float* __restrict__ bias, const float* __restrict__ residual,
    float* __restrict__ C, int M, int N, int K)
{
    __shared__ __align__(16) float As[16][68];
    __shared__ __align__(16) float Bs[16][68];

    const int t  = threadIdx.x;
    const int tx = t & 15;        // 0..15  (column group)
    const int ty = t >> 4;        // 0..15  (row group)
    const int rowBase = blockIdx.y * 64;
    const int colBase = blockIdx.x * 64;

    const int lr = t >> 2;          // 0..63  load row
    const int lc = (t & 3) << 2;    // 0,4,8,12 load col (float4)

    const float* Ag = A + (size_t)(rowBase + lr) * K + lc;
    const float* Wg = W + (size_t)(colBase + lr) * K + lc;

    float acc[4][4] = {};

    for (int k0 = 0; k0 < K; k0 += 16) {
        float4 av = *reinterpret_cast<const float4*>(Ag + k0);
        float4 wv = *reinterpret_cast<const float4*>(Wg + k0);
        As[lc + 0][lr] = av.x; As[lc + 1][lr] = av.y;
        As[lc + 2][lr] = av.z; As[lc + 3][lr] = av.w;
        Bs[lc + 0][lr] = wv.x; Bs[lc + 1][lr] = wv.y;
        Bs[lc + 2][lr] = wv.z; Bs[lc + 3][lr] = wv.w;
        __syncthreads();

#pragma unroll
        for (int kk = 0; kk < 16; kk++) {
            float4 a  = *reinterpret_cast<const float4*>(&As[kk][ty << 2]);
            float4 bq = *reinterpret_cast<const float4*>(&Bs[kk][tx << 2]);
            float ar[4] = {a.x, a.y, a.z, a.w};
            float br[4] = {bq.x, bq.y, bq.z, bq.w};
#pragma unroll
            for (int i = 0; i < 4; i++)
#pragma unroll
                for (int j = 0; j < 4; j++)
                    acc[i][j] = fmaf(ar[i], br[j], acc[i][j]);
        }
        __syncthreads();
    }

#pragma unroll
    for (int i = 0; i < 4; i++) {
        int r = rowBase + (ty << 2) + i;
#pragma unroll
        for (int j = 0; j < 4; j++) {
            int c = colBase + (tx << 2) + j;
            float v = acc[i][j] + bias[c];
            if (residual) v += residual[(size_t)r * N + c];
            C[(size_t)r * N + c] = v;
        }
    }
}

// -------------------- Flash attention (fp32, online softmax) --------------------
// grid: (LQ/64, NH, B); block 256 threads. Per CTA: 64 query rows of one head.
// Shared layout (floats):
//   Qs [HD][64] stride 68   (d-major)
//   Ks [HD][64] stride 68   (d-major)
//   Vs [64][HD] stride 68   (j-major)
//   Ss [64][64] stride 65
//   m[64], l[64], alpha[64]
#define QS_OFF   0
#define KS_OFF   (64 * 68)
#define VS_OFF   (2 * 64 * 68)
#define SS_OFF   (3 * 64 * 68)
#define M_OFF    (SS_OFF + 64 * 65)
#define L_OFF    (M_OFF + 64)
#define AL_OFF   (L_OFF + 64)
#define SMEM_FLOATS (AL_OFF + 64)
#define SMEM_BYTES  (SMEM_FLOATS * 4)

__global__ __launch_bounds__(256) void attn_kernel(
    const float* __restrict__ Q, const float* __restrict__ K,
    const float* __restrict__ V, const int* __restrict__ mask,
    float* __restrict__ ctx)
{
    extern __shared__ __align__(16) float sh[];
    float* Qs = sh + QS_OFF;
    float* Ks = sh + KS_OFF;
    float* Vs = sh + VS_OFF;
    float* Ss = sh + SS_OFF;
    float* mrow_s = sh + M_OFF;
    float* lrow_s = sh + L_OFF;
    float* alp_s  = sh + AL_OFF;

    const int q0 = blockIdx.x * 64;
    const int h  = blockIdx.y;
    const int b  = blockIdx.z;
    const int t  = threadIdx.x;
    const int tx = t & 15;    // column group (key cols / head dims)
    const int ty = t >> 4;    // row group (query rows)

    // load Q tile (d-major)
    for (int idx = t; idx < 64 * 64; idx += 256) {
        int i = idx >> 6, d = idx & 63;
        Qs[d * 68 + i] = Q[(size_t)(b * LQ + q0 + i) * HH + h * HD + d];
    }
    if (t < 64) { mrow_s[t] = -1e30f; lrow_s[t] = 0.f; }

    float acc[4][4] = {};
    const int* mbase = mask + (size_t)(b * LQ + q0) * LK;
    __syncthreads();

    for (int k0 = 0; k0 < LK; k0 += 64) {
        // load K (d-major) and V (j-major) tiles
        for (int idx = t; idx < 64 * 64; idx += 256) {
            int j = idx >> 6, d = idx & 63;
            size_t gk = (size_t)(b * LK + k0 + j) * HH + h * HD + d;
            Ks[d * 68 + j] = K[gk];
            Vs[j * 68 + d] = V[gk];
        }
        __syncthreads();

        // S = Q K^T  (4x4 micro per thread)
        float s[4][4] = {};
#pragma unroll 8
        for (int d = 0; d < 64; d++) {
            float4 a  = *reinterpret_cast<const float4*>(&Qs[d * 68 + (ty << 2)]);
            float4 bv = *reinterpret_cast<const float4*>(&Ks[d * 68 + (tx << 2)]);
            float ar[4] = {a.x, a.y, a.z, a.w};
            float br[4] = {bv.x, bv.y, bv.z, bv.w};
#pragma unroll
            for (int i = 0; i < 4; i++)
#pragma unroll
                for (int j = 0; j < 4; j++)
                    s[i][j] = fmaf(ar[i], br[j], s[i][j]);
        }
        // scale + mask + store to Ss
#pragma unroll
        for (int i = 0; i < 4; i++) {
            int qi = (ty << 2) + i;
            const int* mp = mbase + (size_t)qi * LK + k0 + (tx << 2);
#pragma unroll
            for (int j = 0; j < 4; j++) {
                float v = s[i][j] * 0.125f;   // 1/sqrt(64)
                if (mp[j] == 0) v = -1e9f;
                Ss[qi * 65 + (tx << 2) + j] = v;
            }
        }
        __syncthreads();

        // online softmax update (threads 0..63, one per query row)
        if (t < 64) {
            float mo = mrow_s[t];
            float mn = mo;
#pragma unroll 8
            for (int j = 0; j < 64; j++) mn = fmaxf(mn, Ss[t * 65 + j]);
            float al = __expf(mo - mn);
            float ls = 0.f;
#pragma unroll 8
            for (int j = 0; j < 64; j++) {
                float p = __expf(Ss[t * 65 + j] - mn);
                Ss[t * 65 + j] = p;
                ls += p;
            }
            mrow_s[t] = mn;
            lrow_s[t] = lrow_s[t] * al + ls;
            alp_s[t]  = al;
        }
        __syncthreads();

        // rescale accumulator, then O += P @ V
#pragma unroll
        for (int i = 0; i < 4; i++) {
            float al = alp_s[(ty << 2) + i];
#pragma unroll
            for (int j = 0; j < 4; j++) acc[i][j] *= al;
        }
#pragma unroll 8
        for (int j = 0; j < 64; j++) {
            float4 vv = *reinterpret_cast<const float4*>(&Vs[j * 68 + (tx << 2)]);
            float vr[4] = {vv.x, vv.y, vv.z, vv.w};
            float p[4];
#pragma unroll
            for (int i = 0; i < 4; i++) p[i] = Ss[((ty << 2) + i) * 65 + j];
#pragma unroll
            for (int i = 0; i < 4; i++)
#pragma unroll
                for (int dd = 0; dd < 4; dd++)
                    acc[i][dd] = fmaf(p[i], vr[dd], acc[i][dd]);
        }
        __syncthreads();
    }

    // epilogue: normalize and write ctx in [B*LQ, H] layout
#pragma unroll
    for (int i = 0; i < 4; i++) {
        int qi = (ty << 2) + i;
        float inv = 1.f / lrow_s[qi];
        size_t row = (size_t)(b * LQ + q0 + qi) * HH + h * HD;
#pragma unroll
        for (int j = 0; j < 4; j++)
            ctx[row + (tx << 2) + j] = acc[i][j] * inv;
    }
}

// -------------------- LayerNorm --------------------
__device__ __forceinline__ float block_reduce_sum(float v)
{
    __shared__ float red[8];
    __shared__ float tot;
    __syncthreads();
#pragma unroll
    for (int o = 16; o > 0; o >>= 1) v += __shfl_xor_sync(0xffffffff, v, o);
    int w = threadIdx.x >> 5;
    if ((threadIdx.x & 31) == 0) red[w] = v;
    __syncthreads();
    if (threadIdx.x < 32) {
        float r = (threadIdx.x < 8) ? red[threadIdx.x] : 0.f;
#pragma unroll
        for (int o = 4; o > 0; o >>= 1) r += __shfl_xor_sync(0xffffffff, r, o);
        if (threadIdx.x == 0) tot = r;
    }
    __syncthreads();
    return tot;
}

__global__ __launch_bounds__(256) void ln_kernel(
    const float* __restrict__ X, const float* __restrict__ g,
    const float* __restrict__ bta, float* __restrict__ out)
{
    int row = blockIdx.x;
    const float4 x4 = reinterpret_cast<const float4*>(X + (size_t)row * HH)[threadIdx.x];
    float v[4] = {x4.x, x4.y, x4.z, x4.w};
    float s = v[0] + v[1] + v[2] + v[3];
    float mean = block_reduce_sum(s) * (1.f / (float)HH);
    float d2 = 0.f;
#pragma unroll
    for (int j = 0; j < 4; j++) { float d = v[j] - mean; d2 += d * d; }
    float var = block_reduce_sum(d2) * (1.f / (float)HH);
    float rstd = rsqrtf(var + EPS);
    float4 g4 = reinterpret_cast<const float4*>(g)[threadIdx.x];
    float4 b4 = reinterpret_cast<const float4*>(bta)[threadIdx.x];
    float4 o;
    o.x = (v[0] - mean) * rstd * g4.x + b4.x;
    o.y = (v[1] - mean) * rstd * g4.y + b4.y;
    o.z = (v[2] - mean) * rstd * g4.z + b4.z;
    o.w = (v[3] - mean) * rstd * g4.w + b4.w;
    reinterpret_cast<float4*>(out + (size_t)row * HH)[threadIdx.x] = o;
}

// -------------------- launch --------------------
extern "C" void kernel_launch(void* const* d_in, const int* in_sizes, int n_in,
                              void* d_out, int out_size)
{
    const float* query = (const float*)d_in[0];
    const float* key   = (const float*)d_in[1];
    const float* value = (const float*)d_in[2];
    const int*   mask  = (const int*)d_in[3];
    const float* Wq = (const float*)d_in[4];
    const float* bq = (const float*)d_in[5];
    const float* Wk = (const float*)d_in[6];
    const float* bk = (const float*)d_in[7];
    const float* Wv = (const float*)d_in[8];
    const float* bv = (const float*)d_in[9];
    const float* Wo = (const float*)d_in[10];
    const float* bo = (const float*)d_in[11];
    const float* ln_g = (const float*)d_in[12];
    const float* ln_b = (const float*)d_in[13];
    float* out = (float*)d_out;

    float *gQ, *gK, *gV, *gC, *gX;
    cudaGetSymbolAddress((void**)&gQ, g_Q);
    cudaGetSymbolAddress((void**)&gK, g_K);
    cudaGetSymbolAddress((void**)&gV, g_V);
    cudaGetSymbolAddress((void**)&gC, g_ctx);
    cudaGetSymbolAddress((void**)&gX, g_x);

    cudaFuncSetAttribute(attn_kernel,
                         cudaFuncAttributeMaxDynamicSharedMemorySize, SMEM_BYTES);

    const int Mq = BB * LQ;   // 2048
    const int Mk = BB * LK;   // 4096

    // projections
    gemm_nt_bias<<<dim3(HH / 64, Mq / 64), 256>>>(query, Wq, bq, nullptr, gQ, Mq, HH, HH);
    gemm_nt_bias<<<dim3(HH / 64, Mk / 64), 256>>>(key,   Wk, bk, nullptr, gK, Mk, HH, HH);
    gemm_nt_bias<<<dim3(HH / 64, Mk / 64), 256>>>(value, Wv, bv, nullptr, gV, Mk, HH, HH);

    // attention
    attn_kernel<<<dim3(LQ / 64, NH, BB), 256, SMEM_BYTES>>>(gQ, gK, gV, mask, gC);

    // output projection + residual
    gemm_nt_bias<<<dim3(HH / 64, Mq / 64), 256>>>(gC, Wo, bo, query, gX, Mq, HH, HH);

    // layernorm -> final output
    ln_kernel<<<Mq, 256>>>(gX, ln_g, ln_b, out);
}

// round 2
// speedup vs baseline: 1.5056x; 1.5056x over previous
#include <cuda_runtime.h>
#include <cuda_bf16.h>
#include <math.h>
#include <stdint.h>

// Problem constants (fixed shapes)
#define BB   2
#define LQ   1024
#define LK   2048
#define HH   1024
#define NH   16
#define HD   64
#define EPS  1e-5f

// -------------------- scratch --------------------
__device__ float g_Q[BB * LQ * HH];
__device__ float g_K[BB * LK * HH];
__device__ float g_V[BB * LK * HH];
__device__ float g_ctx[BB * LQ * HH];
__device__ float g_x[BB * LQ * HH];

// -------------------- tf32 helpers --------------------
__device__ __forceinline__ uint32_t f2tf(float f) {
    uint32_t u;
    asm("cvt.rna.tf32.f32 %0, %1;" : "=r"(u) : "f"(f));
    return u;
}

__device__ __forceinline__ void mma8(float* c,
    uint32_t a0, uint32_t a1, uint32_t a2, uint32_t a3,
    uint32_t b0, uint32_t b1)
{
    asm volatile(
        "mma.sync.aligned.m16n8k8.row.col.f32.tf32.tf32.f32 "
        "{%0,%1,%2,%3},{%4,%5,%6,%7},{%8,%9},{%0,%1,%2,%3};"
        : "+f"(c[0]), "+f"(c[1]), "+f"(c[2]), "+f"(c[3])
        : "r"(a0), "r"(a1), "r"(a2), "r"(a3), "r"(b0), "r"(b1));
}

// -------------------- GEMM: C[M,N] = A[M,K] @ W[N,K]^T + bias (+residual) ------
// CTA tile 128x128, BK=32, 256 threads = 8 warps in 4(M) x 2(N), warp tile 32x64.
__global__ __launch_bounds__(256) void gemm_tf32(
    const float* __restrict__ A, const float* __restrict__ W,
    const float* __restrict__ bias, const float* __restrict__ residual,
    float* __restrict__ C, int M, int N, int K)
{
    __shared__ uint32_t As[128][36];
    __shared__ uint32_t Bs[128][36];

    const int t = threadIdx.x, lane = t & 31, warp = t >> 5;
    const int g = lane >> 2, tg = lane & 3;
    const int wm = warp & 3, wn = warp >> 2;
    const int rowBase = blockIdx.y * 128, colBase = blockIdx.x * 128;
    const int lr0 = t >> 3, lc = (t & 7) * 4;

    float acc[2][8][4] = {};

    for (int k0 = 0; k0 < K; k0 += 32) {
#pragma unroll
        for (int r = lr0; r < 128; r += 32) {
            float4 av = *reinterpret_cast<const float4*>(A + (size_t)(rowBase + r) * K + k0 + lc);
            float4 wv = *reinterpret_cast<const float4*>(W + (size_t)(colBase + r) * K + k0 + lc);
            As[r][lc + 0] = f2tf(av.x); As[r][lc + 1] = f2tf(av.y);
            As[r][lc + 2] = f2tf(av.z); As[r][lc + 3] = f2tf(av.w);
            Bs[r][lc + 0] = f2tf(wv.x); Bs[r][lc + 1] = f2tf(wv.y);
            Bs[r][lc + 2] = f2tf(wv.z); Bs[r][lc + 3] = f2tf(wv.w);
        }
        __syncthreads();

#pragma unroll
        for (int kc = 0; kc < 4; kc++) {
            uint32_t af[2][4];
#pragma unroll
            for (int mi = 0; mi < 2; mi++) {
                int r = wm * 32 + mi * 16 + g;
                af[mi][0] = As[r][kc * 8 + tg];
                af[mi][1] = As[r + 8][kc * 8 + tg];
                af[mi][2] = As[r][kc * 8 + 4 + tg];
                af[mi][3] = As[r + 8][kc * 8 + 4 + tg];
            }
#pragma unroll
            for (int ni = 0; ni < 8; ni++) {
                int n = wn * 64 + ni * 8 + g;
                uint32_t b0 = Bs[n][kc * 8 + tg];
                uint32_t b1 = Bs[n][kc * 8 + 4 + tg];
                mma8(acc[0][ni], af[0][0], af[0][1], af[0][2], af[0][3], b0, b1);
                mma8(acc[1][ni], af[1][0], af[1][1], af[1][2], af[1][3], b0, b1);
            }
        }
        __syncthreads();
    }

#pragma unroll
    for (int mi = 0; mi < 2; mi++) {
#pragma unroll
        for (int ni = 0; ni < 8; ni++) {
            int r = rowBase + wm * 32 + mi * 16 + g;
            int c = colBase + wn * 64 + ni * 8 + tg * 2;
            float b0 = bias[c], b1 = bias[c + 1];
            float v0 = acc[mi][ni][0] + b0, v1 = acc[mi][ni][1] + b1;
            float v2 = acc[mi][ni][2] + b0, v3 = acc[mi][ni][3] + b1;
            if (residual) {
                float2 r0 = *reinterpret_cast<const float2*>(residual + (size_t)r * N + c);
                float2 r1 = *reinterpret_cast<const float2*>(residual + (size_t)(r + 8) * N + c);
                v0 += r0.x; v1 += r0.y; v2 += r1.x; v3 += r1.y;
            }
            *reinterpret_cast<float2*>(C + (size_t)r * N + c) = make_float2(v0, v1);
            *reinterpret_cast<float2*>(C + (size_t)(r + 8) * N + c) = make_float2(v2, v3);
        }
    }
}

// -------------------- Flash attention, tf32 mma --------------------
// CTA: 64 q-rows of one (b,h). 256 threads = 8 warps as 4(m-strip of 16) x 2(n-half of 32).
#define SATT_Q 0
#define SATT_K (64 * 68)
#define SATT_V (2 * 64 * 68)
#define SATT_S (3 * 64 * 68)
#define SATT_M (4 * 64 * 68)
#define SATT_L (SATT_M + 64)
#define SATT_A (SATT_L + 64)
#define SATT_WORDS (SATT_A + 64)
#define SATT_BYTES (SATT_WORDS * 4)

__global__ __launch_bounds__(256) void attn_tf32(
    const float* __restrict__ Q, const float* __restrict__ K,
    const float* __restrict__ V, const int* __restrict__ mask,
    float* __restrict__ ctx)
{
    extern __shared__ __align__(16) uint32_t sh[];
    uint32_t* Qs = sh + SATT_Q;
    uint32_t* Ks = sh + SATT_K;
    uint32_t* Vt = sh + SATT_V;               // [d][j]  (V transposed)
    float*    Ss = reinterpret_cast<float*>(sh + SATT_S);
    float*    mS = reinterpret_cast<float*>(sh + SATT_M);
    float*    lS = reinterpret_cast<float*>(sh + SATT_L);
    float*    aS = reinterpret_cast<float*>(sh + SATT_A);

    const int q0 = blockIdx.x * 64, h = blockIdx.y, b = blockIdx.z;
    const int t = threadIdx.x, lane = t & 31, warp = t >> 5;
    const int g = lane >> 2, tg = lane & 3;
    const int strip = warp & 3, half = warp >> 2;
    const int rq = strip * 16 + g;

    for (int idx = t; idx < 4096; idx += 256) {
        int i = idx >> 6, d = idx & 63;
        Qs[i * 68 + d] = f2tf(Q[(size_t)(b * LQ + q0 + i) * HH + h * HD + d]);
    }
    if (t < 64) { mS[t] = -1e30f; lS[t] = 0.f; }

    float acc_o[4][4] = {};
    const int* mbase = mask + (size_t)(b * LQ + q0) * LK;
    __syncthreads();

    for (int k0 = 0; k0 < LK; k0 += 64) {
        // load K (j-major) and V (transposed, d-major)
        for (int idx = t; idx < 4096; idx += 256) {
            int j = idx >> 6, d = idx & 63;
            size_t gk = (size_t)(b * LK + k0 + j) * HH + h * HD + d;
            Ks[j * 68 + d] = f2tf(K[gk]);
            Vt[d * 68 + j] = f2tf(V[gk]);
        }
        __syncthreads();

        // S = Q K^T  (each warp: 16x32 strip)
        float s[4][4] = {};
#pragma unroll
        for (int kc = 0; kc < 8; kc++) {
            uint32_t a0 = Qs[rq * 68 + kc * 8 + tg];
            uint32_t a1 = Qs[(rq + 8) * 68 + kc * 8 + tg];
            uint32_t a2 = Qs[rq * 68 + kc * 8 + 4 + tg];
            uint32_t a3 = Qs[(rq + 8) * 68 + kc * 8 + 4 + tg];
#pragma unroll
            for (int ni = 0; ni < 4; ni++) {
                int n = half * 32 + ni * 8 + g;
                uint32_t b0 = Ks[n * 68 + kc * 8 + tg];
                uint32_t b1 = Ks[n * 68 + kc * 8 + 4 + tg];
                mma8(s[ni], a0, a1, a2, a3, b0, b1);
            }
        }
        // scale + mask -> Ss
#pragma unroll
        for (int ni = 0; ni < 4; ni++) {
            int kc2 = half * 32 + ni * 8 + tg * 2;
            int2 m0 = *reinterpret_cast<const int2*>(mbase + (size_t)rq * LK + k0 + kc2);
            int2 m1 = *reinterpret_cast<const int2*>(mbase + (size_t)(rq + 8) * LK + k0 + kc2);
            float v0 = (m0.x == 0) ? -1e9f : s[ni][0] * 0.125f;
            float v1 = (m0.y == 0) ? -1e9f : s[ni][1] * 0.125f;
            float v2 = (m1.x == 0) ? -1e9f : s[ni][2] * 0.125f;
            float v3 = (m1.y == 0) ? -1e9f : s[ni][3] * 0.125f;
            *reinterpret_cast<float2*>(&Ss[rq * 68 + kc2]) = make_float2(v0, v1);
            *reinterpret_cast<float2*>(&Ss[(rq + 8) * 68 + kc2]) = make_float2(v2, v3);
        }
        __syncthreads();

        // online softmax: 4 threads per row
        {
            int row = t >> 2, seg = t & 3;
            float* p = Ss + row * 68 + seg * 16;
            float mo = mS[row];
            float mx = mo;
#pragma unroll
            for (int e = 0; e < 16; e++) mx = fmaxf(mx, p[e]);
            mx = fmaxf(mx, __shfl_xor_sync(0xffffffff, mx, 1));
            mx = fmaxf(mx, __shfl_xor_sync(0xffffffff, mx, 2));
            float ssum = 0.f;
#pragma unroll
            for (int e = 0; e < 16; e++) {
                uint32_t u = f2tf(__expf(p[e] - mx));   // store as tf32-exact value
                float pv = __uint_as_float(u);
                p[e] = pv;
                ssum += pv;
            }
            ssum += __shfl_xor_sync(0xffffffff, ssum, 1);
            ssum += __shfl_xor_sync(0xffffffff, ssum, 2);
            if (seg == 0) {
                float al = __expf(mo - mx);
                mS[row] = mx;
                lS[row] = lS[row] * al + ssum;
                aS[row] = al;
            }
        }
        __syncthreads();

        // rescale accumulator, then O += P @ V
        {
            float al0 = aS[rq], al1 = aS[rq + 8];
#pragma unroll
            for (int ni = 0; ni < 4; ni++) {
                acc_o[ni][0] *= al0; acc_o[ni][1] *= al0;
                acc_o[ni][2] *= al1; acc_o[ni][3] *= al1;
            }
            const uint32_t* Su = reinterpret_cast<const uint32_t*>(Ss);
#pragma unroll
            for (int kc = 0; kc < 8; kc++) {
                uint32_t a0 = Su[rq * 68 + kc * 8 + tg];
                uint32_t a1 = Su[(rq + 8) * 68 + kc * 8 + tg];
                uint32_t a2 = Su[rq * 68 + kc * 8 + 4 + tg];
                uint32_t a3 = Su[(rq + 8) * 68 + kc * 8 + 4 + tg];
#pragma unroll
                for (int ni = 0; ni < 4; ni++) {
                    int dn = half * 32 + ni * 8 + g;
                    uint32_t b0 = Vt[dn * 68 + kc * 8 + tg];
                    uint32_t b1 = Vt[dn * 68 + kc * 8 + 4 + tg];
                    mma8(acc_o[ni], a0, a1, a2, a3, b0, b1);
                }
            }
        }
        __syncthreads();
    }

    // epilogue
    {
        float inv0 = 1.f / lS[rq], inv1 = 1.f / lS[rq + 8];
#pragma unroll
        for (int ni = 0; ni < 4; ni++) {
            int c = half * 32 + ni * 8 + tg * 2;
            size_t r0 = (size_t)(b * LQ + q0 + rq) * HH + h * HD + c;
            size_t r1 = (size_t)(b * LQ + q0 + rq + 8) * HH + h * HD + c;
            *reinterpret_cast<float2*>(ctx + r0) = make_float2(acc_o[ni][0] * inv0, acc_o[ni][1] * inv0);
            *reinterpret_cast<float2*>(ctx + r1) = make_float2(acc_o[ni][2] * inv1, acc_o[ni][3] * inv1);
        }
    }
}

// -------------------- LayerNorm --------------------
__device__ __forceinline__ float block_reduce_sum(float v)
{
    __shared__ float red[8];
    __shared__ float tot;
    __syncthreads();
#pragma unroll
    for (int o = 16; o > 0; o >>= 1) v += __shfl_xor_sync(0xffffffff, v, o);
    int w = threadIdx.x >> 5;
    if ((threadIdx.x & 31) == 0) red[w] = v;
    __syncthreads();
    if (threadIdx.x < 32) {
        float r = (threadIdx.x < 8) ? red[threadIdx.x] : 0.f;
#pragma unroll
        for (int o = 4; o > 0; o >>= 1) r += __shfl_xor_sync(0xffffffff, r, o);
        if (threadIdx.x == 0) tot = r;
    }
    __syncthreads();
    return tot;
}

__global__ __launch_bounds__(256) void ln_kernel(
    const float* __restrict__ X, const float* __restrict__ g,
    const float* __restrict__ bta, float* __restrict__ out)
{
    int row = blockIdx.x;
    const float4 x4 = reinterpret_cast<const float4*>(X + (size_t)row * HH)[threadIdx.x];
    float v[4] = {x4.x, x4.y, x4.z, x4.w};
    float s = v[0] + v[1] + v[2] + v[3];
    float mean = block_reduce_sum(s) * (1.f / (float)HH);
    float d2 = 0.f;
#pragma unroll
    for (int j = 0; j < 4; j++) { float d = v[j] - mean; d2 += d * d; }
    float var = block_reduce_sum(d2) * (1.f / (float)HH);
    float rstd = rsqrtf(var + EPS);
    float4 g4 = reinterpret_cast<const float4*>(g)[threadIdx.x];
    float4 b4 = reinterpret_cast<const float4*>(bta)[threadIdx.x];
    float4 o;
    o.x = (v[0] - mean) * rstd * g4.x + b4.x;
    o.y = (v[1] - mean) * rstd * g4.y + b4.y;
    o.z = (v[2] - mean) * rstd * g4.z + b4.z;
    o.w = (v[3] - mean) * rstd * g4.w + b4.w;
    reinterpret_cast<float4*>(out + (size_t)row * HH)[threadIdx.x] = o;
}

// -------------------- launch --------------------
extern "C" void kernel_launch(void* const* d_in, const int* in_sizes, int n_in,
                              void* d_out, int out_size)
{
    const float* query = (const float*)d_in[0];
    const float* key   = (const float*)d_in[1];
    const float* value = (const float*)d_in[2];
    const int*   mask  = (const int*)d_in[3];
    const float* Wq = (const float*)d_in[4];
    const float* bq = (const float*)d_in[5];
    const float* Wk = (const float*)d_in[6];
    const float* bk = (const float*)d_in[7];
    const float* Wv = (const float*)d_in[8];
    const float* bv = (const float*)d_in[9];
    const float* Wo = (const float*)d_in[10];
    const float* bo = (const float*)d_in[11];
    const float* ln_g = (const float*)d_in[12];
    const float* ln_b = (const float*)d_in[13];
    float* out = (float*)d_out;

    float *gQ, *gK, *gV, *gC, *gX;
    cudaGetSymbolAddress((void**)&gQ, g_Q);
    cudaGetSymbolAddress((void**)&gK, g_K);
    cudaGetSymbolAddress((void**)&gV, g_V);
    cudaGetSymbolAddress((void**)&gC, g_ctx);
    cudaGetSymbolAddress((void**)&gX, g_x);

    cudaFuncSetAttribute(attn_tf32,
                         cudaFuncAttributeMaxDynamicSharedMemorySize, SATT_BYTES);

    const int Mq = BB * LQ;   // 2048
    const int Mk = BB * LK;   // 4096

    gemm_tf32<<<dim3(HH / 128, Mq / 128), 256>>>(query, Wq, bq, nullptr, gQ, Mq, HH, HH);
    gemm_tf32<<<dim3(HH / 128, Mk / 128), 256>>>(key,   Wk, bk, nullptr, gK, Mk, HH, HH);
    gemm_tf32<<<dim3(HH / 128, Mk / 128), 256>>>(value, Wv, bv, nullptr, gV, Mk, HH, HH);

    attn_tf32<<<dim3(LQ / 64, NH, BB), 256, SATT_BYTES>>>(gQ, gK, gV, mask, gC);

    gemm_tf32<<<dim3(HH / 128, Mq / 128), 256>>>(gC, Wo, bo, query, gX, Mq, HH, HH);

    ln_kernel<<<Mq, 256>>>(gX, ln_g, ln_b, out);
}

// round 3
// speedup vs baseline: 2.8841x; 1.9156x over previous
#include <cuda_runtime.h>
#include <cuda_bf16.h>
#include <math.h>
#include <stdint.h>

// Problem constants (fixed shapes)
#define BB   2
#define LQ   1024
#define LK   2048
#define HH   1024
#define NH   16
#define HD   64
#define EPS  1e-5f

// -------------------- scratch --------------------
__device__ float g_Q[BB * LQ * HH];
__device__ float g_K[BB * LK * HH];
__device__ float g_V[BB * LK * HH];
__device__ float g_ctx[BB * LQ * HH];
__device__ float g_x[BB * LQ * HH];

// -------------------- helpers --------------------
__device__ __forceinline__ uint32_t smaddr(const void* p) {
    return (uint32_t)__cvta_generic_to_shared(p);
}
__device__ __forceinline__ void cp16(uint32_t dst, const void* src) {
    asm volatile("cp.async.cg.shared.global [%0], [%1], 16;" :: "r"(dst), "l"(src));
}
__device__ __forceinline__ void cp_commit() {
    asm volatile("cp.async.commit_group;");
}
__device__ __forceinline__ void cp_wait0() {
    asm volatile("cp.async.wait_group 0;");
}

// tf32 mma: raw fp32 registers are truncated to tf32 by the tensor core.
__device__ __forceinline__ void mma8(float* c,
    uint32_t a0, uint32_t a1, uint32_t a2, uint32_t a3,
    uint32_t b0, uint32_t b1)
{
    asm volatile(
        "mma.sync.aligned.m16n8k8.row.col.f32.tf32.tf32.f32 "
        "{%0,%1,%2,%3},{%4,%5,%6,%7},{%8,%9},{%0,%1,%2,%3};"
        : "+f"(c[0]), "+f"(c[1]), "+f"(c[2]), "+f"(c[3])
        : "r"(a0), "r"(a1), "r"(a2), "r"(a3), "r"(b0), "r"(b1));
}

// -------------------- GEMM: C[M,N] = A[M,K] @ W[N,K]^T + bias (+residual) ------
// CTA 128x128, BK=32, double-buffered cp.async. 256 threads = 8 warps (4M x 2N),
// warp tile 32x64.
#define GSTG (128 * 36)             // words per matrix per stage
#define GEMM_SMEM_BYTES (4 * GSTG * 4)

__global__ __launch_bounds__(256) void gemm_tf32(
    const float* __restrict__ A, const float* __restrict__ W,
    const float* __restrict__ bias, const float* __restrict__ residual,
    float* __restrict__ C, int M, int N, int K)
{
    extern __shared__ __align__(16) uint32_t sm[];
    uint32_t* AsBase = sm;                 // [2][128][36]
    uint32_t* BsBase = sm + 2 * GSTG;      // [2][128][36]

    const int t = threadIdx.x, lane = t & 31, warp = t >> 5;
    const int g = lane >> 2, tg = lane & 3;
    const int wm = warp & 3, wn = warp >> 2;
    const int rowBase = blockIdx.y * 128, colBase = blockIdx.x * 128;

    const int lr = t >> 3;              // load row base (0..31)
    const int lc = (t & 7) * 4;         // load col (float4)
    const uint32_t smA = smaddr(AsBase);
    const uint32_t smB = smaddr(BsBase);

    auto loadStage = [&](int s, int k0) {
        uint32_t offA = smA + (uint32_t)s * GSTG * 4;
        uint32_t offB = smB + (uint32_t)s * GSTG * 4;
#pragma unroll
        for (int i = 0; i < 4; i++) {
            int r = lr + 32 * i;
            cp16(offA + (r * 36 + lc) * 4, A + (size_t)(rowBase + r) * K + k0 + lc);
            cp16(offB + (r * 36 + lc) * 4, W + (size_t)(colBase + r) * K + k0 + lc);
        }
    };

    loadStage(0, 0);
    cp_commit();

    float acc[2][8][4] = {};
    const int nst = K / 32;

    for (int s = 0; s < nst; s++) {
        cp_wait0();
        __syncthreads();
        if (s + 1 < nst) { loadStage((s + 1) & 1, (s + 1) * 32); cp_commit(); }

        const uint32_t* Ac = AsBase + (s & 1) * GSTG;
        const uint32_t* Bc = BsBase + (s & 1) * GSTG;

#pragma unroll
        for (int kc = 0; kc < 4; kc++) {
            uint32_t af[2][4];
#pragma unroll
            for (int mi = 0; mi < 2; mi++) {
                int r = wm * 32 + mi * 16 + g;
                af[mi][0] = Ac[r * 36 + kc * 8 + tg];
                af[mi][1] = Ac[(r + 8) * 36 + kc * 8 + tg];
                af[mi][2] = Ac[r * 36 + kc * 8 + 4 + tg];
                af[mi][3] = Ac[(r + 8) * 36 + kc * 8 + 4 + tg];
            }
#pragma unroll
            for (int ni = 0; ni < 8; ni++) {
                int n = wn * 64 + ni * 8 + g;
                uint32_t b0 = Bc[n * 36 + kc * 8 + tg];
                uint32_t b1 = Bc[n * 36 + kc * 8 + 4 + tg];
                mma8(acc[0][ni], af[0][0], af[0][1], af[0][2], af[0][3], b0, b1);
                mma8(acc[1][ni], af[1][0], af[1][1], af[1][2], af[1][3], b0, b1);
            }
        }
    }

#pragma unroll
    for (int mi = 0; mi < 2; mi++) {
#pragma unroll
        for (int ni = 0; ni < 8; ni++) {
            int r = rowBase + wm * 32 + mi * 16 + g;
            int c = colBase + wn * 64 + ni * 8 + tg * 2;
            float b0 = bias[c], b1 = bias[c + 1];
            float v0 = acc[mi][ni][0] + b0, v1 = acc[mi][ni][1] + b1;
            float v2 = acc[mi][ni][2] + b0, v3 = acc[mi][ni][3] + b1;
            if (residual) {
                float2 r0 = *reinterpret_cast<const float2*>(residual + (size_t)r * N + c);
                float2 r1 = *reinterpret_cast<const float2*>(residual + (size_t)(r + 8) * N + c);
                v0 += r0.x; v1 += r0.y; v2 += r1.x; v3 += r1.y;
            }
            *reinterpret_cast<float2*>(C + (size_t)r * N + c) = make_float2(v0, v1);
            *reinterpret_cast<float2*>(C + (size_t)(r + 8) * N + c) = make_float2(v2, v3);
        }
    }
}

// -------------------- Flash attention, tf32 mma, cp.async double-buffered -------
// CTA: 64 q-rows of one (b,h). 256 threads = 8 warps (4 strips of 16 rows x 2
// column halves of 32). K/V tiles (64 keys) double-buffered, raw fp32 layout.
#define TSTG (64 * 68)      // words per K or V tile
#define SATT_Q 0
#define SATT_K TSTG                    // [2][64][68]
#define SATT_V (3 * TSTG)              // [2][64][68]
#define SATT_S (5 * TSTG)
#define SATT_M (6 * TSTG)
#define SATT_L (SATT_M + 64)
#define SATT_A (SATT_L + 64)
#define SATT_WORDS (SATT_A + 64)
#define SATT_BYTES (SATT_WORDS * 4)

__global__ __launch_bounds__(256) void attn_tf32(
    const float* __restrict__ Q, const float* __restrict__ K,
    const float* __restrict__ V, const int* __restrict__ mask,
    float* __restrict__ ctx)
{
    extern __shared__ __align__(16) uint32_t sh[];
    uint32_t* Qs = sh + SATT_Q;
    uint32_t* KsB = sh + SATT_K;
    uint32_t* VsB = sh + SATT_V;
    float*    Ss = reinterpret_cast<float*>(sh + SATT_S);
    float*    mS = reinterpret_cast<float*>(sh + SATT_M);
    float*    lS = reinterpret_cast<float*>(sh + SATT_L);
    float*    aS = reinterpret_cast<float*>(sh + SATT_A);

    const int q0 = blockIdx.x * 64, h = blockIdx.y, b = blockIdx.z;
    const int t = threadIdx.x, lane = t & 31, warp = t >> 5;
    const int g = lane >> 2, tg = lane & 3;
    const int strip = warp & 3, half = warp >> 2;
    const int rq = strip * 16 + g;

    const int ldr = t >> 4;            // 0..15  row base for loads
    const int ldc = (t & 15) * 4;      // float4 col
    const uint32_t smQ = smaddr(Qs), smK = smaddr(KsB), smV = smaddr(VsB);

    // prologue: Q tile + K/V stage 0
#pragma unroll
    for (int i = 0; i < 4; i++) {
        int r = ldr + 16 * i;
        cp16(smQ + (r * 68 + ldc) * 4, Q + (size_t)(b * LQ + q0 + r) * HH + h * HD + ldc);
    }
    auto loadKV = [&](int s, int k0) {
#pragma unroll
        for (int i = 0; i < 4; i++) {
            int r = ldr + 16 * i;
            size_t gofs = (size_t)(b * LK + k0 + r) * HH + h * HD + ldc;
            uint32_t sofs = (uint32_t)(s * TSTG + r * 68 + ldc) * 4;
            cp16(smK + sofs, K + gofs);
            cp16(smV + sofs, V + gofs);
        }
    };
    loadKV(0, 0);
    cp_commit();

    if (t < 64) { mS[t] = -1e30f; lS[t] = 0.f; }

    float acc_o[4][4] = {};
    const int* mbase = mask + (size_t)(b * LQ + q0) * LK;
    const int NT = LK / 64;

    for (int kt = 0; kt < NT; kt++) {
        cp_wait0();
        __syncthreads();
        if (kt + 1 < NT) { loadKV((kt + 1) & 1, (kt + 1) * 64); cp_commit(); }

        const uint32_t* Kc = KsB + (kt & 1) * TSTG;
        const uint32_t* Vc = VsB + (kt & 1) * TSTG;

        // prefetch mask into regs
        int2 mk0[4], mk1[4];
#pragma unroll
        for (int ni = 0; ni < 4; ni++) {
            int kc2 = half * 32 + ni * 8 + tg * 2;
            mk0[ni] = *reinterpret_cast<const int2*>(mbase + (size_t)rq * LK + kt * 64 + kc2);
            mk1[ni] = *reinterpret_cast<const int2*>(mbase + (size_t)(rq + 8) * LK + kt * 64 + kc2);
        }

        // S = Q K^T
        float s[4][4] = {};
#pragma unroll
        for (int kc = 0; kc < 8; kc++) {
            uint32_t a0 = Qs[rq * 68 + kc * 8 + tg];
            uint32_t a1 = Qs[(rq + 8) * 68 + kc * 8 + tg];
            uint32_t a2 = Qs[rq * 68 + kc * 8 + 4 + tg];
            uint32_t a3 = Qs[(rq + 8) * 68 + kc * 8 + 4 + tg];
#pragma unroll
            for (int ni = 0; ni < 4; ni++) {
                int n = half * 32 + ni * 8 + g;
                uint32_t b0 = Kc[n * 68 + kc * 8 + tg];
                uint32_t b1 = Kc[n * 68 + kc * 8 + 4 + tg];
                mma8(s[ni], a0, a1, a2, a3, b0, b1);
            }
        }
        // scale + mask -> Ss
#pragma unroll
        for (int ni = 0; ni < 4; ni++) {
            int kc2 = half * 32 + ni * 8 + tg * 2;
            float v0 = (mk0[ni].x == 0) ? -1e9f : s[ni][0] * 0.125f;
            float v1 = (mk0[ni].y == 0) ? -1e9f : s[ni][1] * 0.125f;
            float v2 = (mk1[ni].x == 0) ? -1e9f : s[ni][2] * 0.125f;
            float v3 = (mk1[ni].y == 0) ? -1e9f : s[ni][3] * 0.125f;
            *reinterpret_cast<float2*>(&Ss[rq * 68 + kc2]) = make_float2(v0, v1);
            *reinterpret_cast<float2*>(&Ss[(rq + 8) * 68 + kc2]) = make_float2(v2, v3);
        }
        __syncthreads();

        // online softmax: 4 threads per row, vectorized
        {
            int row = t >> 2, seg = t & 3;
            float4* p = reinterpret_cast<float4*>(Ss + row * 68 + seg * 16);
            float4 v[4];
#pragma unroll
            for (int e = 0; e < 4; e++) v[e] = p[e];
            float mo = mS[row];
            float mx = mo;
#pragma unroll
            for (int e = 0; e < 4; e++) {
                mx = fmaxf(mx, fmaxf(fmaxf(v[e].x, v[e].y), fmaxf(v[e].z, v[e].w)));
            }
            mx = fmaxf(mx, __shfl_xor_sync(0xffffffff, mx, 1));
            mx = fmaxf(mx, __shfl_xor_sync(0xffffffff, mx, 2));
            float ssum = 0.f;
#pragma unroll
            for (int e = 0; e < 4; e++) {
                v[e].x = __expf(v[e].x - mx); v[e].y = __expf(v[e].y - mx);
                v[e].z = __expf(v[e].z - mx); v[e].w = __expf(v[e].w - mx);
                ssum += v[e].x + v[e].y + v[e].z + v[e].w;
                p[e] = v[e];
            }
            ssum += __shfl_xor_sync(0xffffffff, ssum, 1);
            ssum += __shfl_xor_sync(0xffffffff, ssum, 2);
            if (seg == 0) {
                float al = __expf(mo - mx);
                mS[row] = mx;
                lS[row] = lS[row] * al + ssum;
                aS[row] = al;
            }
        }
        __syncthreads();

        // rescale accumulator, then O += P @ V   (V raw [j][d] layout)
        {
            float al0 = aS[rq], al1 = aS[rq + 8];
#pragma unroll
            for (int ni = 0; ni < 4; ni++) {
                acc_o[ni][0] *= al0; acc_o[ni][1] *= al0;
                acc_o[ni][2] *= al1; acc_o[ni][3] *= al1;
            }
            const uint32_t* Su = reinterpret_cast<const uint32_t*>(Ss);
#pragma unroll
            for (int kc = 0; kc < 8; kc++) {
                uint32_t a0 = Su[rq * 68 + kc * 8 + tg];
                uint32_t a1 = Su[(rq + 8) * 68 + kc * 8 + tg];
                uint32_t a2 = Su[rq * 68 + kc * 8 + 4 + tg];
                uint32_t a3 = Su[(rq + 8) * 68 + kc * 8 + 4 + tg];
#pragma unroll
                for (int ni = 0; ni < 4; ni++) {
                    int dn = half * 32 + ni * 8 + g;
                    uint32_t b0 = Vc[(kc * 8 + tg) * 68 + dn];
                    uint32_t b1 = Vc[(kc * 8 + 4 + tg) * 68 + dn];
                    mma8(acc_o[ni], a0, a1, a2, a3, b0, b1);
                }
            }
        }
    }

    __syncthreads();
    // epilogue
    {
        float inv0 = 1.f / lS[rq], inv1 = 1.f / lS[rq + 8];
#pragma unroll
        for (int ni = 0; ni < 4; ni++) {
            int c = half * 32 + ni * 8 + tg * 2;
            size_t r0 = (size_t)(b * LQ + q0 + rq) * HH + h * HD + c;
            size_t r1 = (size_t)(b * LQ + q0 + rq + 8) * HH + h * HD + c;
            *reinterpret_cast<float2*>(ctx + r0) = make_float2(acc_o[ni][0] * inv0, acc_o[ni][1] * inv0);
            *reinterpret_cast<float2*>(ctx + r1) = make_float2(acc_o[ni][2] * inv1, acc_o[ni][3] * inv1);
        }
    }
}

// -------------------- LayerNorm --------------------
__device__ __forceinline__ float block_reduce_sum(float v)
{
    __shared__ float red[8];
    __shared__ float tot;
    __syncthreads();
#pragma unroll
    for (int o = 16; o > 0; o >>= 1) v += __shfl_xor_sync(0xffffffff, v, o);
    int w = threadIdx.x >> 5;
    if ((threadIdx.x & 31) == 0) red[w] = v;
    __syncthreads();
    if (threadIdx.x < 32) {
        float r = (threadIdx.x < 8) ? red[threadIdx.x] : 0.f;
#pragma unroll
        for (int o = 4; o > 0; o >>= 1) r += __shfl_xor_sync(0xffffffff, r, o);
        if (threadIdx.x == 0) tot = r;
    }
    __syncthreads();
    return tot;
}

__global__ __launch_bounds__(256) void ln_kernel(
    const float* __restrict__ X, const float* __restrict__ g,
    const float* __restrict__ bta, float* __restrict__ out)
{
    int row = blockIdx.x;
    const float4 x4 = reinterpret_cast<const float4*>(X + (size_t)row * HH)[threadIdx.x];
    float v[4] = {x4.x, x4.y, x4.z, x4.w};
    float s = v[0] + v[1] + v[2] + v[3];
    float mean = block_reduce_sum(s) * (1.f / (float)HH);
    float d2 = 0.f;
#pragma unroll
    for (int j = 0; j < 4; j++) { float d = v[j] - mean; d2 += d * d; }
    float var = block_reduce_sum(d2) * (1.f / (float)HH);
    float rstd = rsqrtf(var + EPS);
    float4 g4 = reinterpret_cast<const float4*>(g)[threadIdx.x];
    float4 b4 = reinterpret_cast<const float4*>(bta)[threadIdx.x];
    float4 o;
    o.x = (v[0] - mean) * rstd * g4.x + b4.x;
    o.y = (v[1] - mean) * rstd * g4.y + b4.y;
    o.z = (v[2] - mean) * rstd * g4.z + b4.z;
    o.w = (v[3] - mean) * rstd * g4.w + b4.w;
    reinterpret_cast<float4*>(out + (size_t)row * HH)[threadIdx.x] = o;
}

// -------------------- launch --------------------
extern "C" void kernel_launch(void* const* d_in, const int* in_sizes, int n_in,
                              void* d_out, int out_size)
{
    const float* query = (const float*)d_in[0];
    const float* key   = (const float*)d_in[1];
    const float* value = (const float*)d_in[2];
    const int*   mask  = (const int*)d_in[3];
    const float* Wq = (const float*)d_in[4];
    const float* bq = (const float*)d_in[5];
    const float* Wk = (const float*)d_in[6];
    const float* bk = (const float*)d_in[7];
    const float* Wv = (const float*)d_in[8];
    const float* bv = (const float*)d_in[9];
    const float* Wo = (const float*)d_in[10];
    const float* bo = (const float*)d_in[11];
    const float* ln_g = (const float*)d_in[12];
    const float* ln_b = (const float*)d_in[13];
    float* out = (float*)d_out;

    float *gQ, *gK, *gV, *gC, *gX;
    cudaGetSymbolAddress((void**)&gQ, g_Q);
    cudaGetSymbolAddress((void**)&gK, g_K);
    cudaGetSymbolAddress((void**)&gV, g_V);
    cudaGetSymbolAddress((void**)&gC, g_ctx);
    cudaGetSymbolAddress((void**)&gX, g_x);

    cudaFuncSetAttribute(gemm_tf32,
                         cudaFuncAttributeMaxDynamicSharedMemorySize, GEMM_SMEM_BYTES);
    cudaFuncSetAttribute(attn_tf32,
                         cudaFuncAttributeMaxDynamicSharedMemorySize, SATT_BYTES);

    const int Mq = BB * LQ;   // 2048
    const int Mk = BB * LK;   // 4096

    gemm_tf32<<<dim3(HH / 128, Mq / 128), 256, GEMM_SMEM_BYTES>>>(query, Wq, bq, nullptr, gQ, Mq, HH, HH);
    gemm_tf32<<<dim3(HH / 128, Mk / 128), 256, GEMM_SMEM_BYTES>>>(key,   Wk, bk, nullptr, gK, Mk, HH, HH);
    gemm_tf32<<<dim3(HH / 128, Mk / 128), 256, GEMM_SMEM_BYTES>>>(value, Wv, bv, nullptr, gV, Mk, HH, HH);

    attn_tf32<<<dim3(LQ / 64, NH, BB), 256, SATT_BYTES>>>(gQ, gK, gV, mask, gC);

    gemm_tf32<<<dim3(HH / 128, Mq / 128), 256, GEMM_SMEM_BYTES>>>(gC, Wo, bo, query, gX, Mq, HH, HH);

    ln_kernel<<<Mq, 256>>>(gX, ln_g, ln_b, out);
}

// round 4
// speedup vs baseline: 3.2283x; 1.1193x over previous
#include <cuda_runtime.h>
#include <cuda_bf16.h>
#include <math.h>
#include <stdint.h>

// Problem constants (fixed shapes)
#define BB   2
#define LQ   1024
#define LK   2048
#define HH   1024
#define NH   16
#define HD   64
#define EPS  1e-5f

// -------------------- scratch --------------------
__device__ float g_Q[BB * LQ * HH];
__device__ float g_K[BB * LK * HH];
__device__ float g_V[BB * LK * HH];
__device__ float g_ctx[BB * LQ * HH];
__device__ float g_x[BB * LQ * HH];

// -------------------- helpers --------------------
__device__ __forceinline__ uint32_t smaddr(const void* p) {
    return (uint32_t)__cvta_generic_to_shared(p);
}
__device__ __forceinline__ void cp16(uint32_t dst, const void* src) {
    asm volatile("cp.async.cg.shared.global [%0], [%1], 16;" :: "r"(dst), "l"(src));
}
__device__ __forceinline__ void cp_commit() {
    asm volatile("cp.async.commit_group;");
}
__device__ __forceinline__ void cp_wait0() {
    asm volatile("cp.async.wait_group 0;");
}

// tf32 mma: raw fp32 registers are truncated to tf32 by the tensor core.
__device__ __forceinline__ void mma8(float* c,
    uint32_t a0, uint32_t a1, uint32_t a2, uint32_t a3,
    uint32_t b0, uint32_t b1)
{
    asm volatile(
        "mma.sync.aligned.m16n8k8.row.col.f32.tf32.tf32.f32 "
        "{%0,%1,%2,%3},{%4,%5,%6,%7},{%8,%9},{%0,%1,%2,%3};"
        : "+f"(c[0]), "+f"(c[1]), "+f"(c[2]), "+f"(c[3])
        : "r"(a0), "r"(a1), "r"(a2), "r"(a3), "r"(b0), "r"(b1));
}

// -------------------- GEMM: C[M,N] = A[M,K] @ W[N,K]^T + bias (+residual) ------
// CTA 128x128, BK=32, double-buffered cp.async. 256 threads = 8 warps (4M x 2N).
#define GSTG (128 * 36)
#define GEMM_SMEM_BYTES (4 * GSTG * 4)

__global__ __launch_bounds__(256) void gemm_tf32(
    const float* __restrict__ A, const float* __restrict__ W,
    const float* __restrict__ bias, const float* __restrict__ residual,
    float* __restrict__ C, int M, int N, int K)
{
    extern __shared__ __align__(16) uint32_t sm[];
    uint32_t* AsBase = sm;
    uint32_t* BsBase = sm + 2 * GSTG;

    const int t = threadIdx.x, lane = t & 31, warp = t >> 5;
    const int g = lane >> 2, tg = lane & 3;
    const int wm = warp & 3, wn = warp >> 2;
    const int rowBase = blockIdx.y * 128, colBase = blockIdx.x * 128;

    const int lr = t >> 3;
    const int lc = (t & 7) * 4;
    const uint32_t smA = smaddr(AsBase);
    const uint32_t smB = smaddr(BsBase);

    auto loadStage = [&](int s, int k0) {
        uint32_t offA = smA + (uint32_t)s * GSTG * 4;
        uint32_t offB = smB + (uint32_t)s * GSTG * 4;
#pragma unroll
        for (int i = 0; i < 4; i++) {
            int r = lr + 32 * i;
            cp16(offA + (r * 36 + lc) * 4, A + (size_t)(rowBase + r) * K + k0 + lc);
            cp16(offB + (r * 36 + lc) * 4, W + (size_t)(colBase + r) * K + k0 + lc);
        }
    };

    loadStage(0, 0);
    cp_commit();

    float acc[2][8][4] = {};
    const int nst = K / 32;

    for (int s = 0; s < nst; s++) {
        cp_wait0();
        __syncthreads();
        if (s + 1 < nst) { loadStage((s + 1) & 1, (s + 1) * 32); cp_commit(); }

        const uint32_t* Ac = AsBase + (s & 1) * GSTG;
        const uint32_t* Bc = BsBase + (s & 1) * GSTG;

#pragma unroll
        for (int kc = 0; kc < 4; kc++) {
            uint32_t af[2][4];
#pragma unroll
            for (int mi = 0; mi < 2; mi++) {
                int r = wm * 32 + mi * 16 + g;
                af[mi][0] = Ac[r * 36 + kc * 8 + tg];
                af[mi][1] = Ac[(r + 8) * 36 + kc * 8 + tg];
                af[mi][2] = Ac[r * 36 + kc * 8 + 4 + tg];
                af[mi][3] = Ac[(r + 8) * 36 + kc * 8 + 4 + tg];
            }
#pragma unroll
            for (int ni = 0; ni < 8; ni++) {
                int n = wn * 64 + ni * 8 + g;
                uint32_t b0 = Bc[n * 36 + kc * 8 + tg];
                uint32_t b1 = Bc[n * 36 + kc * 8 + 4 + tg];
                mma8(acc[0][ni], af[0][0], af[0][1], af[0][2], af[0][3], b0, b1);
                mma8(acc[1][ni], af[1][0], af[1][1], af[1][2], af[1][3], b0, b1);
            }
        }
    }

#pragma unroll
    for (int mi = 0; mi < 2; mi++) {
#pragma unroll
        for (int ni = 0; ni < 8; ni++) {
            int r = rowBase + wm * 32 + mi * 16 + g;
            int c = colBase + wn * 64 + ni * 8 + tg * 2;
            float b0 = bias[c], b1 = bias[c + 1];
            float v0 = acc[mi][ni][0] + b0, v1 = acc[mi][ni][1] + b1;
            float v2 = acc[mi][ni][2] + b0, v3 = acc[mi][ni][3] + b1;
            if (residual) {
                float2 r0 = *reinterpret_cast<const float2*>(residual + (size_t)r * N + c);
                float2 r1 = *reinterpret_cast<const float2*>(residual + (size_t)(r + 8) * N + c);
                v0 += r0.x; v1 += r0.y; v2 += r1.x; v3 += r1.y;
            }
            *reinterpret_cast<float2*>(C + (size_t)r * N + c) = make_float2(v0, v1);
            *reinterpret_cast<float2*>(C + (size_t)(r + 8) * N + c) = make_float2(v2, v3);
        }
    }
}

// -------------------- Flash attention v3 --------------------
// CTA: 64 q-rows of one (b,h), 128 threads = 4 warps. Each warp owns 16 rows x
// ALL 64 key-columns -> full score rows live inside one lane-quad:
// softmax entirely in registers (quad shuffles), P round-trip is warp-local.
// One __syncthreads per k-tile (K/V buffer rotation only).
#define TSTG (64 * 68)
#define A_Q 0
#define A_K TSTG                 // [2][64][68]
#define A_V (3 * TSTG)           // [2][64][68]
#define A_P (5 * TSTG)           // [64][68]
#define A_WORDS (6 * TSTG)
#define A_BYTES (A_WORDS * 4)    // 104448 bytes -> 2 CTAs/SM

__global__ __launch_bounds__(128) void attn_tf32(
    const float* __restrict__ Q, const float* __restrict__ K,
    const float* __restrict__ V, const int* __restrict__ mask,
    float* __restrict__ ctx)
{
    extern __shared__ __align__(16) uint32_t sh[];
    uint32_t* Qs  = sh + A_Q;
    uint32_t* KsB = sh + A_K;
    uint32_t* VsB = sh + A_V;
    float*    Ps  = reinterpret_cast<float*>(sh + A_P);
    const uint32_t* Pu = sh + A_P;

    const int q0 = blockIdx.x * 64, h = blockIdx.y, b = blockIdx.z;
    const int t = threadIdx.x, lane = t & 31, warp = t >> 5;
    const int g = lane >> 2, tg = lane & 3;
    const int rq0 = warp * 16 + g, rq1 = rq0 + 8;

    const int ldr = t >> 4;            // 0..7
    const int ldc = (t & 15) * 4;
    const uint32_t smQ = smaddr(Qs), smK = smaddr(KsB), smV = smaddr(VsB);

    // prologue: Q tile + K/V stage 0
#pragma unroll
    for (int i = 0; i < 8; i++) {
        int r = ldr + 8 * i;
        cp16(smQ + (r * 68 + ldc) * 4, Q + (size_t)(b * LQ + q0 + r) * HH + h * HD + ldc);
    }
    auto loadKV = [&](int s, int k0) {
#pragma unroll
        for (int i = 0; i < 8; i++) {
            int r = ldr + 8 * i;
            size_t gofs = (size_t)(b * LK + k0 + r) * HH + h * HD + ldc;
            uint32_t sofs = (uint32_t)(s * TSTG + r * 68 + ldc) * 4;
            cp16(smK + sofs, K + gofs);
            cp16(smV + sofs, V + gofs);
        }
    };
    loadKV(0, 0);
    cp_commit();

    float acc_o[8][4] = {};
    float m0 = -1e30f, m1 = -1e30f, l0 = 0.f, l1 = 0.f;
    const int* mbase = mask + (size_t)(b * LQ + q0) * LK;
    const int NT = LK / 64;

    for (int kt = 0; kt < NT; kt++) {
        cp_wait0();
        __syncthreads();
        if (kt + 1 < NT) { loadKV((kt + 1) & 1, (kt + 1) * 64); cp_commit(); }

        const uint32_t* Kc = KsB + (kt & 1) * TSTG;
        const uint32_t* Vc = VsB + (kt & 1) * TSTG;

        // prefetch mask (rows rq0, rq1; 16 cols each)
        int2 mk0[8], mk1[8];
#pragma unroll
        for (int ni = 0; ni < 8; ni++) {
            int c = ni * 8 + tg * 2;
            mk0[ni] = *reinterpret_cast<const int2*>(mbase + (size_t)rq0 * LK + kt * 64 + c);
            mk1[ni] = *reinterpret_cast<const int2*>(mbase + (size_t)rq1 * LK + kt * 64 + c);
        }

        // S = Q K^T : warp covers 16 rows x 64 cols
        float s[8][4] = {};
#pragma unroll
        for (int kc = 0; kc < 8; kc++) {
            uint32_t a0 = Qs[rq0 * 68 + kc * 8 + tg];
            uint32_t a1 = Qs[rq1 * 68 + kc * 8 + tg];
            uint32_t a2 = Qs[rq0 * 68 + kc * 8 + 4 + tg];
            uint32_t a3 = Qs[rq1 * 68 + kc * 8 + 4 + tg];
#pragma unroll
            for (int ni = 0; ni < 8; ni++) {
                int n = ni * 8 + g;
                uint32_t b0 = Kc[n * 68 + kc * 8 + tg];
                uint32_t b1 = Kc[n * 68 + kc * 8 + 4 + tg];
                mma8(s[ni], a0, a1, a2, a3, b0, b1);
            }
        }

        // mask + scale, row max in registers (quad shuffle)
        float mx0 = m0, mx1 = m1;
#pragma unroll
        for (int ni = 0; ni < 8; ni++) {
            s[ni][0] = (mk0[ni].x == 0) ? -1e9f : s[ni][0] * 0.125f;
            s[ni][1] = (mk0[ni].y == 0) ? -1e9f : s[ni][1] * 0.125f;
            s[ni][2] = (mk1[ni].x == 0) ? -1e9f : s[ni][2] * 0.125f;
            s[ni][3] = (mk1[ni].y == 0) ? -1e9f : s[ni][3] * 0.125f;
            mx0 = fmaxf(mx0, fmaxf(s[ni][0], s[ni][1]));
            mx1 = fmaxf(mx1, fmaxf(s[ni][2], s[ni][3]));
        }
        mx0 = fmaxf(mx0, __shfl_xor_sync(0xffffffff, mx0, 1));
        mx0 = fmaxf(mx0, __shfl_xor_sync(0xffffffff, mx0, 2));
        mx1 = fmaxf(mx1, __shfl_xor_sync(0xffffffff, mx1, 1));
        mx1 = fmaxf(mx1, __shfl_xor_sync(0xffffffff, mx1, 2));

        float al0 = __expf(m0 - mx0), al1 = __expf(m1 - mx1);
        float ls0 = 0.f, ls1 = 0.f;
#pragma unroll
        for (int ni = 0; ni < 8; ni++) {
            s[ni][0] = __expf(s[ni][0] - mx0);
            s[ni][1] = __expf(s[ni][1] - mx0);
            s[ni][2] = __expf(s[ni][2] - mx1);
            s[ni][3] = __expf(s[ni][3] - mx1);
            ls0 += s[ni][0] + s[ni][1];
            ls1 += s[ni][2] + s[ni][3];
        }
        ls0 += __shfl_xor_sync(0xffffffff, ls0, 1);
        ls0 += __shfl_xor_sync(0xffffffff, ls0, 2);
        ls1 += __shfl_xor_sync(0xffffffff, ls1, 1);
        ls1 += __shfl_xor_sync(0xffffffff, ls1, 2);
        l0 = l0 * al0 + ls0;  m0 = mx0;
        l1 = l1 * al1 + ls1;  m1 = mx1;

        // rescale accumulator; stage P into warp-local smem
#pragma unroll
        for (int ni = 0; ni < 8; ni++) {
            acc_o[ni][0] *= al0; acc_o[ni][1] *= al0;
            acc_o[ni][2] *= al1; acc_o[ni][3] *= al1;
            int c = ni * 8 + tg * 2;
            *reinterpret_cast<float2*>(&Ps[rq0 * 68 + c]) = make_float2(s[ni][0], s[ni][1]);
            *reinterpret_cast<float2*>(&Ps[rq1 * 68 + c]) = make_float2(s[ni][2], s[ni][3]);
        }
        __syncwarp();

        // O += P @ V   (V raw [j][d] layout; B-operand = V columns)
#pragma unroll
        for (int kc = 0; kc < 8; kc++) {
            uint32_t a0 = Pu[rq0 * 68 + kc * 8 + tg];
            uint32_t a1 = Pu[rq1 * 68 + kc * 8 + tg];
            uint32_t a2 = Pu[rq0 * 68 + kc * 8 + 4 + tg];
            uint32_t a3 = Pu[rq1 * 68 + kc * 8 + 4 + tg];
#pragma unroll
            for (int ni = 0; ni < 8; ni++) {
                int dn = ni * 8 + g;
                uint32_t b0 = Vc[(kc * 8 + tg) * 68 + dn];
                uint32_t b1 = Vc[(kc * 8 + 4 + tg) * 68 + dn];
                mma8(acc_o[ni], a0, a1, a2, a3, b0, b1);
            }
        }
        __syncwarp();
    }

    // epilogue (l in registers)
    {
        float inv0 = 1.f / l0, inv1 = 1.f / l1;
#pragma unroll
        for (int ni = 0; ni < 8; ni++) {
            int c = ni * 8 + tg * 2;
            size_t r0 = (size_t)(b * LQ + q0 + rq0) * HH + h * HD + c;
            size_t r1 = (size_t)(b * LQ + q0 + rq1) * HH + h * HD + c;
            *reinterpret_cast<float2*>(ctx + r0) = make_float2(acc_o[ni][0] * inv0, acc_o[ni][1] * inv0);
            *reinterpret_cast<float2*>(ctx + r1) = make_float2(acc_o[ni][2] * inv1, acc_o[ni][3] * inv1);
        }
    }
}

// -------------------- LayerNorm --------------------
__device__ __forceinline__ float block_reduce_sum(float v)
{
    __shared__ float red[8];
    __shared__ float tot;
    __syncthreads();
#pragma unroll
    for (int o = 16; o > 0; o >>= 1) v += __shfl_xor_sync(0xffffffff, v, o);
    int w = threadIdx.x >> 5;
    if ((threadIdx.x & 31) == 0) red[w] = v;
    __syncthreads();
    if (threadIdx.x < 32) {
        float r = (threadIdx.x < 8) ? red[threadIdx.x] : 0.f;
#pragma unroll
        for (int o = 4; o > 0; o >>= 1) r += __shfl_xor_sync(0xffffffff, r, o);
        if (threadIdx.x == 0) tot = r;
    }
    __syncthreads();
    return tot;
}

__global__ __launch_bounds__(256) void ln_kernel(
    const float* __restrict__ X, const float* __restrict__ g,
    const float* __restrict__ bta, float* __restrict__ out)
{
    int row = blockIdx.x;
    const float4 x4 = reinterpret_cast<const float4*>(X + (size_t)row * HH)[threadIdx.x];
    float v[4] = {x4.x, x4.y, x4.z, x4.w};
    float s = v[0] + v[1] + v[2] + v[3];
    float mean = block_reduce_sum(s) * (1.f / (float)HH);
    float d2 = 0.f;
#pragma unroll
    for (int j = 0; j < 4; j++) { float d = v[j] - mean; d2 += d * d; }
    float var = block_reduce_sum(d2) * (1.f / (float)HH);
    float rstd = rsqrtf(var + EPS);
    float4 g4 = reinterpret_cast<const float4*>(g)[threadIdx.x];
    float4 b4 = reinterpret_cast<const float4*>(bta)[threadIdx.x];
    float4 o;
    o.x = (v[0] - mean) * rstd * g4.x + b4.x;
    o.y = (v[1] - mean) * rstd * g4.y + b4.y;
    o.z = (v[2] - mean) * rstd * g4.z + b4.z;
    o.w = (v[3] - mean) * rstd * g4.w + b4.w;
    reinterpret_cast<float4*>(out + (size_t)row * HH)[threadIdx.x] = o;
}

// -------------------- launch --------------------
extern "C" void kernel_launch(void* const* d_in, const int* in_sizes, int n_in,
                              void* d_out, int out_size)
{
    const float* query = (const float*)d_in[0];
    const float* key   = (const float*)d_in[1];
    const float* value = (const float*)d_in[2];
    const int*   mask  = (const int*)d_in[3];
    const float* Wq = (const float*)d_in[4];
    const float* bq = (const float*)d_in[5];
    const float* Wk = (const float*)d_in[6];
    const float* bk = (const float*)d_in[7];
    const float* Wv = (const float*)d_in[8];
    const float* bv = (const float*)d_in[9];
    const float* Wo = (const float*)d_in[10];
    const float* bo = (const float*)d_in[11];
    const float* ln_g = (const float*)d_in[12];
    const float* ln_b = (const float*)d_in[13];
    float* out = (float*)d_out;

    float *gQ, *gK, *gV, *gC, *gX;
    cudaGetSymbolAddress((void**)&gQ, g_Q);
    cudaGetSymbolAddress((void**)&gK, g_K);
    cudaGetSymbolAddress((void**)&gV, g_V);
    cudaGetSymbolAddress((void**)&gC, g_ctx);
    cudaGetSymbolAddress((void**)&gX, g_x);

    cudaFuncSetAttribute(gemm_tf32,
                         cudaFuncAttributeMaxDynamicSharedMemorySize, GEMM_SMEM_BYTES);
    cudaFuncSetAttribute(attn_tf32,
                         cudaFuncAttributeMaxDynamicSharedMemorySize, A_BYTES);

    const int Mq = BB * LQ;   // 2048
    const int Mk = BB * LK;   // 4096

    gemm_tf32<<<dim3(HH / 128, Mq / 128), 256, GEMM_SMEM_BYTES>>>(query, Wq, bq, nullptr, gQ, Mq, HH, HH);
    gemm_tf32<<<dim3(HH / 128, Mk / 128), 256, GEMM_SMEM_BYTES>>>(key,   Wk, bk, nullptr, gK, Mk, HH, HH);
    gemm_tf32<<<dim3(HH / 128, Mk / 128), 256, GEMM_SMEM_BYTES>>>(value, Wv, bv, nullptr, gV, Mk, HH, HH);

    attn_tf32<<<dim3(LQ / 64, NH, BB), 128, A_BYTES>>>(gQ, gK, gV, mask, gC);

    gemm_tf32<<<dim3(HH / 128, Mq / 128), 256, GEMM_SMEM_BYTES>>>(gC, Wo, bo, query, gX, Mq, HH, HH);

    ln_kernel<<<Mq, 256>>>(gX, ln_g, ln_b, out);
}

// round 5
// speedup vs baseline: 3.8085x; 1.1797x over previous
#include <cuda_runtime.h>
#include <cuda_bf16.h>
#include <math.h>
#include <stdint.h>

// Problem constants (fixed shapes)
#define BB   2
#define LQ   1024
#define LK   2048
#define HH   1024
#define NH   16
#define HD   64
#define EPS  1e-5f

// -------------------- scratch --------------------
__device__ float g_Q[BB * LQ * HH];
__device__ float g_K[BB * LK * HH];
__device__ float g_V[BB * LK * HH];
__device__ float g_ctx[BB * LQ * HH];
__device__ float g_x[BB * LQ * HH];

// -------------------- helpers --------------------
__device__ __forceinline__ uint32_t smaddr(const void* p) {
    return (uint32_t)__cvta_generic_to_shared(p);
}
__device__ __forceinline__ void cp16(uint32_t dst, const void* src) {
    asm volatile("cp.async.cg.shared.global [%0], [%1], 16;" :: "r"(dst), "l"(src));
}
__device__ __forceinline__ void cp_commit() {
    asm volatile("cp.async.commit_group;");
}
__device__ __forceinline__ void cp_wait0() {
    asm volatile("cp.async.wait_group 0;");
}

// tf32 mma: raw fp32 registers are truncated to tf32 by the tensor core.
__device__ __forceinline__ void mma8(float* c,
    uint32_t a0, uint32_t a1, uint32_t a2, uint32_t a3,
    uint32_t b0, uint32_t b1)
{
    asm volatile(
        "mma.sync.aligned.m16n8k8.row.col.f32.tf32.tf32.f32 "
        "{%0,%1,%2,%3},{%4,%5,%6,%7},{%8,%9},{%0,%1,%2,%3};"
        : "+f"(c[0]), "+f"(c[1]), "+f"(c[2]), "+f"(c[3])
        : "r"(a0), "r"(a1), "r"(a2), "r"(a3), "r"(b0), "r"(b1));
}

// -------------------- GEMM: C[M,N] = A[M,K] @ W[N,K]^T + bias (+residual) ------
// CTA 128x128, BK=32, double-buffered cp.async. 256 threads = 8 warps (4M x 2N).
#define GSTG (128 * 36)
#define GEMM_SMEM_BYTES (4 * GSTG * 4)

__global__ __launch_bounds__(256) void gemm_tf32(
    const float* __restrict__ A, const float* __restrict__ W,
    const float* __restrict__ bias, const float* __restrict__ residual,
    float* __restrict__ C, int M, int N, int K)
{
    extern __shared__ __align__(16) uint32_t sm[];
    uint32_t* AsBase = sm;
    uint32_t* BsBase = sm + 2 * GSTG;

    const int t = threadIdx.x, lane = t & 31, warp = t >> 5;
    const int g = lane >> 2, tg = lane & 3;
    const int wm = warp & 3, wn = warp >> 2;
    const int rowBase = blockIdx.y * 128, colBase = blockIdx.x * 128;

    const int lr = t >> 3;
    const int lc = (t & 7) * 4;
    const uint32_t smA = smaddr(AsBase);
    const uint32_t smB = smaddr(BsBase);

    auto loadStage = [&](int s, int k0) {
        uint32_t offA = smA + (uint32_t)s * GSTG * 4;
        uint32_t offB = smB + (uint32_t)s * GSTG * 4;
#pragma unroll
        for (int i = 0; i < 4; i++) {
            int r = lr + 32 * i;
            cp16(offA + (r * 36 + lc) * 4, A + (size_t)(rowBase + r) * K + k0 + lc);
            cp16(offB + (r * 36 + lc) * 4, W + (size_t)(colBase + r) * K + k0 + lc);
        }
    };

    loadStage(0, 0);
    cp_commit();

    float acc[2][8][4] = {};
    const int nst = K / 32;

    for (int s = 0; s < nst; s++) {
        cp_wait0();
        __syncthreads();
        if (s + 1 < nst) { loadStage((s + 1) & 1, (s + 1) * 32); cp_commit(); }

        const uint32_t* Ac = AsBase + (s & 1) * GSTG;
        const uint32_t* Bc = BsBase + (s & 1) * GSTG;

#pragma unroll
        for (int kc = 0; kc < 4; kc++) {
            uint32_t af[2][4];
#pragma unroll
            for (int mi = 0; mi < 2; mi++) {
                int r = wm * 32 + mi * 16 + g;
                af[mi][0] = Ac[r * 36 + kc * 8 + tg];
                af[mi][1] = Ac[(r + 8) * 36 + kc * 8 + tg];
                af[mi][2] = Ac[r * 36 + kc * 8 + 4 + tg];
                af[mi][3] = Ac[(r + 8) * 36 + kc * 8 + 4 + tg];
            }
#pragma unroll
            for (int ni = 0; ni < 8; ni++) {
                int n = wn * 64 + ni * 8 + g;
                uint32_t b0 = Bc[n * 36 + kc * 8 + tg];
                uint32_t b1 = Bc[n * 36 + kc * 8 + 4 + tg];
                mma8(acc[0][ni], af[0][0], af[0][1], af[0][2], af[0][3], b0, b1);
                mma8(acc[1][ni], af[1][0], af[1][1], af[1][2], af[1][3], b0, b1);
            }
        }
    }

#pragma unroll
    for (int mi = 0; mi < 2; mi++) {
#pragma unroll
        for (int ni = 0; ni < 8; ni++) {
            int r = rowBase + wm * 32 + mi * 16 + g;
            int c = colBase + wn * 64 + ni * 8 + tg * 2;
            float b0 = bias[c], b1 = bias[c + 1];
            float v0 = acc[mi][ni][0] + b0, v1 = acc[mi][ni][1] + b1;
            float v2 = acc[mi][ni][2] + b0, v3 = acc[mi][ni][3] + b1;
            if (residual) {
                float2 r0 = *reinterpret_cast<const float2*>(residual + (size_t)r * N + c);
                float2 r1 = *reinterpret_cast<const float2*>(residual + (size_t)(r + 8) * N + c);
                v0 += r0.x; v1 += r0.y; v2 += r1.x; v3 += r1.y;
            }
            *reinterpret_cast<float2*>(C + (size_t)r * N + c) = make_float2(v0, v1);
            *reinterpret_cast<float2*>(C + (size_t)(r + 8) * N + c) = make_float2(v2, v3);
        }
    }
}

// -------------------- Flash attention v4 --------------------
// CTA: 128 q-rows of one (b,h), 256 threads = 8 warps; warp = 16 rows x 64 cols.
// Q fragments live in registers (staged once through P-smem). K stride 68,
// V stride 72 (conflict-free B-fragment banks), P stride 68.
#define KSTG (64 * 68)
#define VSTG (64 * 72)
#define A_K 0
#define A_V (2 * KSTG)
#define A_P (2 * KSTG + 2 * VSTG)
#define A_WORDS (A_P + 128 * 68)
#define A_BYTES (A_WORDS * 4)          // 106496 bytes -> 2 CTAs/SM, 16 warps

__global__ __launch_bounds__(256, 2) void attn_tf32(
    const float* __restrict__ Q, const float* __restrict__ K,
    const float* __restrict__ V, const int* __restrict__ mask,
    float* __restrict__ ctx)
{
    extern __shared__ __align__(16) uint32_t sh[];
    uint32_t* KsB = sh + A_K;
    uint32_t* VsB = sh + A_V;
    float*    Ps  = reinterpret_cast<float*>(sh + A_P);
    const uint32_t* Pu = sh + A_P;

    const int q0 = blockIdx.x * 128, h = blockIdx.y, b = blockIdx.z;
    const int t = threadIdx.x, lane = t & 31, warp = t >> 5;
    const int g = lane >> 2, tg = lane & 3;
    const int rq0 = warp * 16 + g, rq1 = rq0 + 8;

    const int ldr = t >> 4;            // 0..15
    const int ldc = (t & 15) * 4;
    const uint32_t smK = smaddr(KsB), smV = smaddr(VsB), smP = smaddr(Ps);

    // stage Q tile (coalesced) into the P region
#pragma unroll
    for (int i = 0; i < 8; i++) {
        int r = ldr + 16 * i;
        cp16(smP + (r * 68 + ldc) * 4, Q + (size_t)(b * LQ + q0 + r) * HH + h * HD + ldc);
    }
    auto loadKV = [&](int s, int k0) {
#pragma unroll
        for (int i = 0; i < 4; i++) {
            int r = ldr + 16 * i;
            size_t gofs = (size_t)(b * LK + k0 + r) * HH + h * HD + ldc;
            cp16(smK + (uint32_t)(s * KSTG + r * 68 + ldc) * 4, K + gofs);
            cp16(smV + (uint32_t)(s * VSTG + r * 72 + ldc) * 4, V + gofs);
        }
    };
    loadKV(0, 0);
    cp_commit();
    cp_wait0();
    __syncthreads();

    // Q fragments -> registers (reused for all 32 k-tiles)
    uint32_t qf[8][4];
#pragma unroll
    for (int kc = 0; kc < 8; kc++) {
        qf[kc][0] = Pu[rq0 * 68 + kc * 8 + tg];
        qf[kc][1] = Pu[rq1 * 68 + kc * 8 + tg];
        qf[kc][2] = Pu[rq0 * 68 + kc * 8 + 4 + tg];
        qf[kc][3] = Pu[rq1 * 68 + kc * 8 + 4 + tg];
    }
    __syncthreads();    // P region now free

    float acc_o[8][4] = {};
    float m0 = -1e30f, m1 = -1e30f, l0 = 0.f, l1 = 0.f;
    const int* mbase = mask + (size_t)(b * LQ + q0) * LK;
    const int NT = LK / 64;

    for (int kt = 0; kt < NT; kt++) {
        if (kt + 1 < NT) { loadKV((kt + 1) & 1, (kt + 1) * 64); cp_commit(); }

        const uint32_t* Kc = KsB + (kt & 1) * KSTG;
        const uint32_t* Vc = VsB + (kt & 1) * VSTG;

        // prefetch mask (rows rq0, rq1; 16 cols each)
        int2 mk0[8], mk1[8];
#pragma unroll
        for (int ni = 0; ni < 8; ni++) {
            int c = ni * 8 + tg * 2;
            mk0[ni] = *reinterpret_cast<const int2*>(mbase + (size_t)rq0 * LK + kt * 64 + c);
            mk1[ni] = *reinterpret_cast<const int2*>(mbase + (size_t)rq1 * LK + kt * 64 + c);
        }

        // S = Q K^T : warp covers 16 rows x 64 cols (Q frags from registers)
        float s[8][4] = {};
#pragma unroll
        for (int kc = 0; kc < 8; kc++) {
#pragma unroll
            for (int ni = 0; ni < 8; ni++) {
                int n = ni * 8 + g;
                uint32_t b0 = Kc[n * 68 + kc * 8 + tg];
                uint32_t b1 = Kc[n * 68 + kc * 8 + 4 + tg];
                mma8(s[ni], qf[kc][0], qf[kc][1], qf[kc][2], qf[kc][3], b0, b1);
            }
        }

        // mask + scale, row max in registers (quad shuffle)
        float mx0 = m0, mx1 = m1;
#pragma unroll
        for (int ni = 0; ni < 8; ni++) {
            s[ni][0] = (mk0[ni].x == 0) ? -1e9f : s[ni][0] * 0.125f;
            s[ni][1] = (mk0[ni].y == 0) ? -1e9f : s[ni][1] * 0.125f;
            s[ni][2] = (mk1[ni].x == 0) ? -1e9f : s[ni][2] * 0.125f;
            s[ni][3] = (mk1[ni].y == 0) ? -1e9f : s[ni][3] * 0.125f;
            mx0 = fmaxf(mx0, fmaxf(s[ni][0], s[ni][1]));
            mx1 = fmaxf(mx1, fmaxf(s[ni][2], s[ni][3]));
        }
        mx0 = fmaxf(mx0, __shfl_xor_sync(0xffffffff, mx0, 1));
        mx0 = fmaxf(mx0, __shfl_xor_sync(0xffffffff, mx0, 2));
        mx1 = fmaxf(mx1, __shfl_xor_sync(0xffffffff, mx1, 1));
        mx1 = fmaxf(mx1, __shfl_xor_sync(0xffffffff, mx1, 2));

        float al0 = __expf(m0 - mx0), al1 = __expf(m1 - mx1);
        float ls0 = 0.f, ls1 = 0.f;
#pragma unroll
        for (int ni = 0; ni < 8; ni++) {
            s[ni][0] = __expf(s[ni][0] - mx0);
            s[ni][1] = __expf(s[ni][1] - mx0);
            s[ni][2] = __expf(s[ni][2] - mx1);
            s[ni][3] = __expf(s[ni][3] - mx1);
            ls0 += s[ni][0] + s[ni][1];
            ls1 += s[ni][2] + s[ni][3];
        }
        ls0 += __shfl_xor_sync(0xffffffff, ls0, 1);
        ls0 += __shfl_xor_sync(0xffffffff, ls0, 2);
        ls1 += __shfl_xor_sync(0xffffffff, ls1, 1);
        ls1 += __shfl_xor_sync(0xffffffff, ls1, 2);
        l0 = l0 * al0 + ls0;  m0 = mx0;
        l1 = l1 * al1 + ls1;  m1 = mx1;

        // rescale accumulator; stage P into warp-local smem
#pragma unroll
        for (int ni = 0; ni < 8; ni++) {
            acc_o[ni][0] *= al0; acc_o[ni][1] *= al0;
            acc_o[ni][2] *= al1; acc_o[ni][3] *= al1;
            int c = ni * 8 + tg * 2;
            *reinterpret_cast<float2*>(&Ps[rq0 * 68 + c]) = make_float2(s[ni][0], s[ni][1]);
            *reinterpret_cast<float2*>(&Ps[rq1 * 68 + c]) = make_float2(s[ni][2], s[ni][3]);
        }
        __syncwarp();

        // O += P @ V   (V [j][d], stride 72: conflict-free B-frag banks)
#pragma unroll
        for (int kc = 0; kc < 8; kc++) {
            uint32_t a0 = Pu[rq0 * 68 + kc * 8 + tg];
            uint32_t a1 = Pu[rq1 * 68 + kc * 8 + tg];
            uint32_t a2 = Pu[rq0 * 68 + kc * 8 + 4 + tg];
            uint32_t a3 = Pu[rq1 * 68 + kc * 8 + 4 + tg];
#pragma unroll
            for (int ni = 0; ni < 8; ni++) {
                int dn = ni * 8 + g;
                uint32_t b0 = Vc[(kc * 8 + tg) * 72 + dn];
                uint32_t b1 = Vc[(kc * 8 + 4 + tg) * 72 + dn];
                mma8(acc_o[ni], a0, a1, a2, a3, b0, b1);
            }
        }

        cp_wait0();
        __syncthreads();    // next K/V stage ready; P consumed
    }

    // epilogue (l in registers)
    {
        float inv0 = 1.f / l0, inv1 = 1.f / l1;
#pragma unroll
        for (int ni = 0; ni < 8; ni++) {
            int c = ni * 8 + tg * 2;
            size_t r0 = (size_t)(b * LQ + q0 + rq0) * HH + h * HD + c;
            size_t r1 = (size_t)(b * LQ + q0 + rq1) * HH + h * HD + c;
            *reinterpret_cast<float2*>(ctx + r0) = make_float2(acc_o[ni][0] * inv0, acc_o[ni][1] * inv0);
            *reinterpret_cast<float2*>(ctx + r1) = make_float2(acc_o[ni][2] * inv1, acc_o[ni][3] * inv1);
        }
    }
}

// -------------------- LayerNorm --------------------
__device__ __forceinline__ float block_reduce_sum(float v)
{
    __shared__ float red[8];
    __shared__ float tot;
    __syncthreads();
#pragma unroll
    for (int o = 16; o > 0; o >>= 1) v += __shfl_xor_sync(0xffffffff, v, o);
    int w = threadIdx.x >> 5;
    if ((threadIdx.x & 31) == 0) red[w] = v;
    __syncthreads();
    if (threadIdx.x < 32) {
        float r = (threadIdx.x < 8) ? red[threadIdx.x] : 0.f;
#pragma unroll
        for (int o = 4; o > 0; o >>= 1) r += __shfl_xor_sync(0xffffffff, r, o);
        if (threadIdx.x == 0) tot = r;
    }
    __syncthreads();
    return tot;
}

__global__ __launch_bounds__(256) void ln_kernel(
    const float* __restrict__ X, const float* __restrict__ g,
    const float* __restrict__ bta, float* __restrict__ out)
{
    int row = blockIdx.x;
    const float4 x4 = reinterpret_cast<const float4*>(X + (size_t)row * HH)[threadIdx.x];
    float v[4] = {x4.x, x4.y, x4.z, x4.w};
    float s = v[0] + v[1] + v[2] + v[3];
    float mean = block_reduce_sum(s) * (1.f / (float)HH);
    float d2 = 0.f;
#pragma unroll
    for (int j = 0; j < 4; j++) { float d = v[j] - mean; d2 += d * d; }
    float var = block_reduce_sum(d2) * (1.f / (float)HH);
    float rstd = rsqrtf(var + EPS);
    float4 g4 = reinterpret_cast<const float4*>(g)[threadIdx.x];
    float4 b4 = reinterpret_cast<const float4*>(bta)[threadIdx.x];
    float4 o;
    o.x = (v[0] - mean) * rstd * g4.x + b4.x;
    o.y = (v[1] - mean) * rstd * g4.y + b4.y;
    o.z = (v[2] - mean) * rstd * g4.z + b4.z;
    o.w = (v[3] - mean) * rstd * g4.w + b4.w;
    reinterpret_cast<float4*>(out + (size_t)row * HH)[threadIdx.x] = o;
}

// -------------------- launch --------------------
extern "C" void kernel_launch(void* const* d_in, const int* in_sizes, int n_in,
                              void* d_out, int out_size)
{
    const float* query = (const float*)d_in[0];
    const float* key   = (const float*)d_in[1];
    const float* value = (const float*)d_in[2];
    const int*   mask  = (const int*)d_in[3];
    const float* Wq = (const float*)d_in[4];
    const float* bq = (const float*)d_in[5];
    const float* Wk = (const float*)d_in[6];
    const float* bk = (const float*)d_in[7];
    const float* Wv = (const float*)d_in[8];
    const float* bv = (const float*)d_in[9];
    const float* Wo = (const float*)d_in[10];
    const float* bo = (const float*)d_in[11];
    const float* ln_g = (const float*)d_in[12];
    const float* ln_b = (const float*)d_in[13];
    float* out = (float*)d_out;

    float *gQ, *gK, *gV, *gC, *gX;
    cudaGetSymbolAddress((void**)&gQ, g_Q);
    cudaGetSymbolAddress((void**)&gK, g_K);
    cudaGetSymbolAddress((void**)&gV, g_V);
    cudaGetSymbolAddress((void**)&gC, g_ctx);
    cudaGetSymbolAddress((void**)&gX, g_x);

    cudaFuncSetAttribute(gemm_tf32,
                         cudaFuncAttributeMaxDynamicSharedMemorySize, GEMM_SMEM_BYTES);
    cudaFuncSetAttribute(attn_tf32,
                         cudaFuncAttributeMaxDynamicSharedMemorySize, A_BYTES);

    const int Mq = BB * LQ;   // 2048
    const int Mk = BB * LK;   // 4096

    gemm_tf32<<<dim3(HH / 128, Mq / 128), 256, GEMM_SMEM_BYTES>>>(query, Wq, bq, nullptr, gQ, Mq, HH, HH);
    gemm_tf32<<<dim3(HH / 128, Mk / 128), 256, GEMM_SMEM_BYTES>>>(key,   Wk, bk, nullptr, gK, Mk, HH, HH);
    gemm_tf32<<<dim3(HH / 128, Mk / 128), 256, GEMM_SMEM_BYTES>>>(value, Wv, bv, nullptr, gV, Mk, HH, HH);

    attn_tf32<<<dim3(LQ / 128, NH, BB), 256, A_BYTES>>>(gQ, gK, gV, mask, gC);

    gemm_tf32<<<dim3(HH / 128, Mq / 128), 256, GEMM_SMEM_BYTES>>>(gC, Wo, bo, query, gX, Mq, HH, HH);

    ln_kernel<<<Mq, 256>>>(gX, ln_g, ln_b, out);
}

// round 6
// speedup vs baseline: 3.8322x; 1.0062x over previous
#include <cuda_runtime.h>
#include <cuda_bf16.h>
#include <math.h>
#include <stdint.h>

// Problem constants (fixed shapes)
#define BB   2
#define LQ   1024
#define LK   2048
#define HH   1024
#define NH   16
#define HD   64
#define EPS  1e-5f

// -------------------- scratch --------------------
__device__ float g_Q[BB * LQ * HH];
__device__ float g_K[BB * LK * HH];
__device__ float g_V[BB * LK * HH];
__device__ float g_ctx[BB * LQ * HH];
__device__ float g_x[BB * LQ * HH];

// -------------------- helpers --------------------
__device__ __forceinline__ uint32_t smaddr(const void* p) {
    return (uint32_t)__cvta_generic_to_shared(p);
}
__device__ __forceinline__ void cp16(uint32_t dst, const void* src) {
    asm volatile("cp.async.cg.shared.global [%0], [%1], 16;" :: "r"(dst), "l"(src));
}
__device__ __forceinline__ void cp_commit() {
    asm volatile("cp.async.commit_group;");
}
__device__ __forceinline__ void cp_wait0() {
    asm volatile("cp.async.wait_group 0;");
}

// tf32 mma: raw fp32 registers are truncated to tf32 by the tensor core.
__device__ __forceinline__ void mma8(float* c,
    uint32_t a0, uint32_t a1, uint32_t a2, uint32_t a3,
    uint32_t b0, uint32_t b1)
{
    asm volatile(
        "mma.sync.aligned.m16n8k8.row.col.f32.tf32.tf32.f32 "
        "{%0,%1,%2,%3},{%4,%5,%6,%7},{%8,%9},{%0,%1,%2,%3};"
        : "+f"(c[0]), "+f"(c[1]), "+f"(c[2]), "+f"(c[3])
        : "r"(a0), "r"(a1), "r"(a2), "r"(a3), "r"(b0), "r"(b1));
}

// -------------------- GEMM: C[M,N] = A[M,K] @ W[N,K]^T + bias (+residual) ------
// CTA 128x128, BK=32, double-buffered cp.async. 256 threads = 8 warps (4M x 2N).
#define GSTG (128 * 36)
#define GEMM_SMEM_BYTES (4 * GSTG * 4)

__global__ __launch_bounds__(256) void gemm_tf32(
    const float* __restrict__ A, const float* __restrict__ W,
    const float* __restrict__ bias, const float* __restrict__ residual,
    float* __restrict__ C, int M, int N, int K)
{
    extern __shared__ __align__(16) uint32_t sm[];
    uint32_t* AsBase = sm;
    uint32_t* BsBase = sm + 2 * GSTG;

    const int t = threadIdx.x, lane = t & 31, warp = t >> 5;
    const int g = lane >> 2, tg = lane & 3;
    const int wm = warp & 3, wn = warp >> 2;
    const int rowBase = blockIdx.y * 128, colBase = blockIdx.x * 128;

    const int lr = t >> 3;
    const int lc = (t & 7) * 4;
    const uint32_t smA = smaddr(AsBase);
    const uint32_t smB = smaddr(BsBase);

    auto loadStage = [&](int s, int k0) {
        uint32_t offA = smA + (uint32_t)s * GSTG * 4;
        uint32_t offB = smB + (uint32_t)s * GSTG * 4;
#pragma unroll
        for (int i = 0; i < 4; i++) {
            int r = lr + 32 * i;
            cp16(offA + (r * 36 + lc) * 4, A + (size_t)(rowBase + r) * K + k0 + lc);
            cp16(offB + (r * 36 + lc) * 4, W + (size_t)(colBase + r) * K + k0 + lc);
        }
    };

    loadStage(0, 0);
    cp_commit();

    float acc[2][8][4] = {};
    const int nst = K / 32;

    for (int s = 0; s < nst; s++) {
        cp_wait0();
        __syncthreads();
        if (s + 1 < nst) { loadStage((s + 1) & 1, (s + 1) * 32); cp_commit(); }

        const uint32_t* Ac = AsBase + (s & 1) * GSTG;
        const uint32_t* Bc = BsBase + (s & 1) * GSTG;

#pragma unroll
        for (int kc = 0; kc < 4; kc++) {
            uint32_t af[2][4];
#pragma unroll
            for (int mi = 0; mi < 2; mi++) {
                int r = wm * 32 + mi * 16 + g;
                af[mi][0] = Ac[r * 36 + kc * 8 + tg];
                af[mi][1] = Ac[(r + 8) * 36 + kc * 8 + tg];
                af[mi][2] = Ac[r * 36 + kc * 8 + 4 + tg];
                af[mi][3] = Ac[(r + 8) * 36 + kc * 8 + 4 + tg];
            }
#pragma unroll
            for (int ni = 0; ni < 8; ni++) {
                int n = wn * 64 + ni * 8 + g;
                uint32_t b0 = Bc[n * 36 + kc * 8 + tg];
                uint32_t b1 = Bc[n * 36 + kc * 8 + 4 + tg];
                mma8(acc[0][ni], af[0][0], af[0][1], af[0][2], af[0][3], b0, b1);
                mma8(acc[1][ni], af[1][0], af[1][1], af[1][2], af[1][3], b0, b1);
            }
        }
    }

#pragma unroll
    for (int mi = 0; mi < 2; mi++) {
#pragma unroll
        for (int ni = 0; ni < 8; ni++) {
            int r = rowBase + wm * 32 + mi * 16 + g;
            int c = colBase + wn * 64 + ni * 8 + tg * 2;
            float b0 = bias[c], b1 = bias[c + 1];
            float v0 = acc[mi][ni][0] + b0, v1 = acc[mi][ni][1] + b1;
            float v2 = acc[mi][ni][2] + b0, v3 = acc[mi][ni][3] + b1;
            if (residual) {
                float2 r0 = *reinterpret_cast<const float2*>(residual + (size_t)r * N + c);
                float2 r1 = *reinterpret_cast<const float2*>(residual + (size_t)(r + 8) * N + c);
                v0 += r0.x; v1 += r0.y; v2 += r1.x; v3 += r1.y;
            }
            *reinterpret_cast<float2*>(C + (size_t)r * N + c) = make_float2(v0, v1);
            *reinterpret_cast<float2*>(C + (size_t)(r + 8) * N + c) = make_float2(v2, v3);
        }
    }
}

// -------------------- Flash attention v5 --------------------
// CTA: 128 q-rows of one (b,h), 128 threads = 4 warps; warp = 32 rows x 64 cols
// (two 16-row mma sub-tiles). B-fragments (K and V) are loaded once and reused
// for 2 mmas -> LDS/mma ~1.25 (halved CTA crossbar traffic vs v4).
#define KSTG (64 * 68)
#define VSTG (64 * 72)
#define A_K 0
#define A_V (2 * KSTG)
#define A_P (2 * KSTG + 2 * VSTG)
#define A_WORDS (A_P + 128 * 68)
#define A_BYTES (A_WORDS * 4)          // 106496 bytes -> 2 CTAs/SM

__global__ __launch_bounds__(128, 2) void attn_tf32(
    const float* __restrict__ Q, const float* __restrict__ K,
    const float* __restrict__ V, const int* __restrict__ mask,
    float* __restrict__ ctx)
{
    extern __shared__ __align__(16) uint32_t sh[];
    uint32_t* KsB = sh + A_K;
    uint32_t* VsB = sh + A_V;
    float*    Ps  = reinterpret_cast<float*>(sh + A_P);
    const uint32_t* Pu = sh + A_P;

    const int q0 = blockIdx.x * 128, h = blockIdx.y, b = blockIdx.z;
    const int t = threadIdx.x, lane = t & 31, warp = t >> 5;
    const int g = lane >> 2, tg = lane & 3;
    const int wbase = warp * 32;

    const int ldr = t >> 4;            // 0..7
    const int ldc = (t & 15) * 4;
    const uint32_t smK = smaddr(KsB), smV = smaddr(VsB), smP = smaddr(Ps);

    // stage Q tile (coalesced) into the P region
#pragma unroll
    for (int i = 0; i < 16; i++) {
        int r = ldr + 8 * i;
        cp16(smP + (r * 68 + ldc) * 4, Q + (size_t)(b * LQ + q0 + r) * HH + h * HD + ldc);
    }
    auto loadKV = [&](int s, int k0) {
#pragma unroll
        for (int i = 0; i < 8; i++) {
            int r = ldr + 8 * i;
            size_t gofs = (size_t)(b * LK + k0 + r) * HH + h * HD + ldc;
            cp16(smK + (uint32_t)(s * KSTG + r * 68 + ldc) * 4, K + gofs);
            cp16(smV + (uint32_t)(s * VSTG + r * 72 + ldc) * 4, V + gofs);
        }
    };
    loadKV(0, 0);
    cp_commit();
    cp_wait0();
    __syncthreads();

    // Q fragments -> registers (2 sub-tiles x 8 kc x 4)
    uint32_t qf[2][8][4];
#pragma unroll
    for (int rt = 0; rt < 2; rt++) {
        int r0 = wbase + rt * 16 + g, r1 = r0 + 8;
#pragma unroll
        for (int kc = 0; kc < 8; kc++) {
            qf[rt][kc][0] = Pu[r0 * 68 + kc * 8 + tg];
            qf[rt][kc][1] = Pu[r1 * 68 + kc * 8 + tg];
            qf[rt][kc][2] = Pu[r0 * 68 + kc * 8 + 4 + tg];
            qf[rt][kc][3] = Pu[r1 * 68 + kc * 8 + 4 + tg];
        }
    }
    __syncthreads();    // P region now free

    float acc[2][8][4] = {};
    float m0[2] = {-1e30f, -1e30f}, m1[2] = {-1e30f, -1e30f};
    float l0[2] = {0.f, 0.f}, l1[2] = {0.f, 0.f};
    const int* mbase = mask + (size_t)(b * LQ + q0) * LK;
    const int NT = LK / 64;

    for (int kt = 0; kt < NT; kt++) {
        if (kt + 1 < NT) { loadKV((kt + 1) & 1, (kt + 1) * 64); cp_commit(); }

        const uint32_t* Kc = KsB + (kt & 1) * KSTG;
        const uint32_t* Vc = VsB + (kt & 1) * VSTG;

        // process the two 16-row sub-tiles sequentially (bounds live registers)
#pragma unroll
        for (int rt = 0; rt < 2; rt++) {
            const int r0 = wbase + rt * 16 + g, r1 = r0 + 8;

            int2 mk0[8], mk1[8];
#pragma unroll
            for (int ni = 0; ni < 8; ni++) {
                int c = ni * 8 + tg * 2;
                mk0[ni] = *reinterpret_cast<const int2*>(mbase + (size_t)r0 * LK + kt * 64 + c);
                mk1[ni] = *reinterpret_cast<const int2*>(mbase + (size_t)r1 * LK + kt * 64 + c);
            }

            // S = Q K^T for this 16x64 sub-tile
            float s[8][4] = {};
#pragma unroll
            for (int kc = 0; kc < 8; kc++) {
#pragma unroll
                for (int ni = 0; ni < 8; ni++) {
                    int n = ni * 8 + g;
                    uint32_t b0 = Kc[n * 68 + kc * 8 + tg];
                    uint32_t b1 = Kc[n * 68 + kc * 8 + 4 + tg];
                    mma8(s[ni], qf[rt][kc][0], qf[rt][kc][1], qf[rt][kc][2], qf[rt][kc][3], b0, b1);
                }
            }

            // mask + scale, row max (quad shuffle)
            float mx0 = m0[rt], mx1 = m1[rt];
#pragma unroll
            for (int ni = 0; ni < 8; ni++) {
                s[ni][0] = (mk0[ni].x == 0) ? -1e9f : s[ni][0] * 0.125f;
                s[ni][1] = (mk0[ni].y == 0) ? -1e9f : s[ni][1] * 0.125f;
                s[ni][2] = (mk1[ni].x == 0) ? -1e9f : s[ni][2] * 0.125f;
                s[ni][3] = (mk1[ni].y == 0) ? -1e9f : s[ni][3] * 0.125f;
                mx0 = fmaxf(mx0, fmaxf(s[ni][0], s[ni][1]));
                mx1 = fmaxf(mx1, fmaxf(s[ni][2], s[ni][3]));
            }
            mx0 = fmaxf(mx0, __shfl_xor_sync(0xffffffff, mx0, 1));
            mx0 = fmaxf(mx0, __shfl_xor_sync(0xffffffff, mx0, 2));
            mx1 = fmaxf(mx1, __shfl_xor_sync(0xffffffff, mx1, 1));
            mx1 = fmaxf(mx1, __shfl_xor_sync(0xffffffff, mx1, 2));

            float al0 = __expf(m0[rt] - mx0), al1 = __expf(m1[rt] - mx1);
            float ls0 = 0.f, ls1 = 0.f;
#pragma unroll
            for (int ni = 0; ni < 8; ni++) {
                s[ni][0] = __expf(s[ni][0] - mx0);
                s[ni][1] = __expf(s[ni][1] - mx0);
                s[ni][2] = __expf(s[ni][2] - mx1);
                s[ni][3] = __expf(s[ni][3] - mx1);
                ls0 += s[ni][0] + s[ni][1];
                ls1 += s[ni][2] + s[ni][3];
            }
            ls0 += __shfl_xor_sync(0xffffffff, ls0, 1);
            ls0 += __shfl_xor_sync(0xffffffff, ls0, 2);
            ls1 += __shfl_xor_sync(0xffffffff, ls1, 1);
            ls1 += __shfl_xor_sync(0xffffffff, ls1, 2);
            l0[rt] = l0[rt] * al0 + ls0;  m0[rt] = mx0;
            l1[rt] = l1[rt] * al1 + ls1;  m1[rt] = mx1;

            // rescale accumulator; stage P into warp-local smem
#pragma unroll
            for (int ni = 0; ni < 8; ni++) {
                acc[rt][ni][0] *= al0; acc[rt][ni][1] *= al0;
                acc[rt][ni][2] *= al1; acc[rt][ni][3] *= al1;
                int c = ni * 8 + tg * 2;
                *reinterpret_cast<float2*>(&Ps[r0 * 68 + c]) = make_float2(s[ni][0], s[ni][1]);
                *reinterpret_cast<float2*>(&Ps[r1 * 68 + c]) = make_float2(s[ni][2], s[ni][3]);
            }
        }
        __syncwarp();

        // O += P @ V : V B-fragments loaded once, used by BOTH row sub-tiles
#pragma unroll
        for (int kc = 0; kc < 8; kc++) {
            uint32_t a[2][4];
#pragma unroll
            for (int rt = 0; rt < 2; rt++) {
                int r0 = wbase + rt * 16 + g, r1 = r0 + 8;
                a[rt][0] = Pu[r0 * 68 + kc * 8 + tg];
                a[rt][1] = Pu[r1 * 68 + kc * 8 + tg];
                a[rt][2] = Pu[r0 * 68 + kc * 8 + 4 + tg];
                a[rt][3] = Pu[r1 * 68 + kc * 8 + 4 + tg];
            }
#pragma unroll
            for (int ni = 0; ni < 8; ni++) {
                int dn = ni * 8 + g;
                uint32_t b0 = Vc[(kc * 8 + tg) * 72 + dn];
                uint32_t b1 = Vc[(kc * 8 + 4 + tg) * 72 + dn];
                mma8(acc[0][ni], a[0][0], a[0][1], a[0][2], a[0][3], b0, b1);
                mma8(acc[1][ni], a[1][0], a[1][1], a[1][2], a[1][3], b0, b1);
            }
        }

        cp_wait0();
        __syncthreads();    // next K/V stage ready; P consumed
    }

    // epilogue
#pragma unroll
    for (int rt = 0; rt < 2; rt++) {
        int r0 = wbase + rt * 16 + g, r1 = r0 + 8;
        float inv0 = 1.f / l0[rt], inv1 = 1.f / l1[rt];
#pragma unroll
        for (int ni = 0; ni < 8; ni++) {
            int c = ni * 8 + tg * 2;
            size_t o0 = (size_t)(b * LQ + q0 + r0) * HH + h * HD + c;
            size_t o1 = (size_t)(b * LQ + q0 + r1) * HH + h * HD + c;
            *reinterpret_cast<float2*>(ctx + o0) = make_float2(acc[rt][ni][0] * inv0, acc[rt][ni][1] * inv0);
            *reinterpret_cast<float2*>(ctx + o1) = make_float2(acc[rt][ni][2] * inv1, acc[rt][ni][3] * inv1);
        }
    }
}

// -------------------- LayerNorm --------------------
__device__ __forceinline__ float block_reduce_sum(float v)
{
    __shared__ float red[8];
    __shared__ float tot;
    __syncthreads();
#pragma unroll
    for (int o = 16; o > 0; o >>= 1) v += __shfl_xor_sync(0xffffffff, v, o);
    int w = threadIdx.x >> 5;
    if ((threadIdx.x & 31) == 0) red[w] = v;
    __syncthreads();
    if (threadIdx.x < 32) {
        float r = (threadIdx.x < 8) ? red[threadIdx.x] : 0.f;
#pragma unroll
        for (int o = 4; o > 0; o >>= 1) r += __shfl_xor_sync(0xffffffff, r, o);
        if (threadIdx.x == 0) tot = r;
    }
    __syncthreads();
    return tot;
}

__global__ __launch_bounds__(256) void ln_kernel(
    const float* __restrict__ X, const float* __restrict__ g,
    const float* __restrict__ bta, float* __restrict__ out)
{
    int row = blockIdx.x;
    const float4 x4 = reinterpret_cast<const float4*>(X + (size_t)row * HH)[threadIdx.x];
    float v[4] = {x4.x, x4.y, x4.z, x4.w};
    float s = v[0] + v[1] + v[2] + v[3];
    float mean = block_reduce_sum(s) * (1.f / (float)HH);
    float d2 = 0.f;
#pragma unroll
    for (int j = 0; j < 4; j++) { float d = v[j] - mean; d2 += d * d; }
    float var = block_reduce_sum(d2) * (1.f / (float)HH);
    float rstd = rsqrtf(var + EPS);
    float4 g4 = reinterpret_cast<const float4*>(g)[threadIdx.x];
    float4 b4 = reinterpret_cast<const float4*>(bta)[threadIdx.x];
    float4 o;
    o.x = (v[0] - mean) * rstd * g4.x + b4.x;
    o.y = (v[1] - mean) * rstd * g4.y + b4.y;
    o.z = (v[2] - mean) * rstd * g4.z + b4.z;
    o.w = (v[3] - mean) * rstd * g4.w + b4.w;
    reinterpret_cast<float4*>(out + (size_t)row * HH)[threadIdx.x] = o;
}

// -------------------- launch --------------------
extern "C" void kernel_launch(void* const* d_in, const int* in_sizes, int n_in,
                              void* d_out, int out_size)
{
    const float* query = (const float*)d_in[0];
    const float* key   = (const float*)d_in[1];
    const float* value = (const float*)d_in[2];
    const int*   mask  = (const int*)d_in[3];
    const float* Wq = (const float*)d_in[4];
    const float* bq = (const float*)d_in[5];
    const float* Wk = (const float*)d_in[6];
    const float* bk = (const float*)d_in[7];
    const float* Wv = (const float*)d_in[8];
    const float* bv = (const float*)d_in[9];
    const float* Wo = (const float*)d_in[10];
    const float* bo = (const float*)d_in[11];
    const float* ln_g = (const float*)d_in[12];
    const float* ln_b = (const float*)d_in[13];
    float* out = (float*)d_out;

    float *gQ, *gK, *gV, *gC, *gX;
    cudaGetSymbolAddress((void**)&gQ, g_Q);
    cudaGetSymbolAddress((void**)&gK, g_K);
    cudaGetSymbolAddress((void**)&gV, g_V);
    cudaGetSymbolAddress((void**)&gC, g_ctx);
    cudaGetSymbolAddress((void**)&gX, g_x);

    cudaFuncSetAttribute(gemm_tf32,
                         cudaFuncAttributeMaxDynamicSharedMemorySize, GEMM_SMEM_BYTES);
    cudaFuncSetAttribute(attn_tf32,
                         cudaFuncAttributeMaxDynamicSharedMemorySize, A_BYTES);

    const int Mq = BB * LQ;   // 2048
    const int Mk = BB * LK;   // 4096

    gemm_tf32<<<dim3(HH / 128, Mq / 128), 256, GEMM_SMEM_BYTES>>>(query, Wq, bq, nullptr, gQ, Mq, HH, HH);
    gemm_tf32<<<dim3(HH / 128, Mk / 128), 256, GEMM_SMEM_BYTES>>>(key,   Wk, bk, nullptr, gK, Mk, HH, HH);
    gemm_tf32<<<dim3(HH / 128, Mk / 128), 256, GEMM_SMEM_BYTES>>>(value, Wv, bv, nullptr, gV, Mk, HH, HH);

    attn_tf32<<<dim3(LQ / 128, NH, BB), 128, A_BYTES>>>(gQ, gK, gV, mask, gC);

    gemm_tf32<<<dim3(HH / 128, Mq / 128), 256, GEMM_SMEM_BYTES>>>(gC, Wo, bo, query, gX, Mq, HH, HH);

    ln_kernel<<<Mq, 256>>>(gX, ln_g, ln_b, out);
}

// round 8
// speedup vs baseline: 5.1368x; 1.3404x over previous
#include <cuda_runtime.h>
#include <cuda_fp16.h>
#include <math.h>
#include <stdint.h>

// Problem constants (fixed shapes)
#define BB   2
#define LQ   1024
#define LK   2048
#define HH   1024
#define NH   16
#define HD   64
#define EPS  1e-5f

// -------------------- scratch --------------------
__device__ __align__(256) __half c_q16[BB * LQ * HH];    // query fp16
__device__ __align__(256) __half c_k16[BB * LK * HH];    // key fp16
__device__ __align__(256) __half c_v16[BB * LK * HH];    // value fp16
__device__ __align__(256) __half w16q[HH * HH];
__device__ __align__(256) __half w16k[HH * HH];
__device__ __align__(256) __half w16v[HH * HH];
__device__ __align__(256) __half w16o[HH * HH];
__device__ __align__(256) __half g_Q16[BB * LQ * HH];    // Q proj (fp16)
__device__ __align__(256) __half g_K16[BB * LK * HH];    // K proj (fp16)
__device__ __align__(256) float  g_V[BB * LK * HH];      // V proj (fp32, PV path)
__device__ __align__(256) __half g_ctx16[BB * LQ * HH];  // attn out (fp16)
__device__ __align__(256) float  g_x[BB * LQ * HH];      // pre-LN

// -------------------- helpers --------------------
__device__ __forceinline__ uint32_t smaddr(const void* p) {
    return (uint32_t)__cvta_generic_to_shared(p);
}
__device__ __forceinline__ void cp16(uint32_t dst, const void* src) {
    asm volatile("cp.async.cg.shared.global [%0], [%1], 16;" :: "r"(dst), "l"(src));
}
__device__ __forceinline__ void cp_commit() {
    asm volatile("cp.async.commit_group;");
}
__device__ __forceinline__ void cp_wait0() {
    asm volatile("cp.async.wait_group 0;");
}

// tf32 mma (PV path in attention)
__device__ __forceinline__ void mma8(float* c,
    uint32_t a0, uint32_t a1, uint32_t a2, uint32_t a3,
    uint32_t b0, uint32_t b1)
{
    asm volatile(
        "mma.sync.aligned.m16n8k8.row.col.f32.tf32.tf32.f32 "
        "{%0,%1,%2,%3},{%4,%5,%6,%7},{%8,%9},{%0,%1,%2,%3};"
        : "+f"(c[0]), "+f"(c[1]), "+f"(c[2]), "+f"(c[3])
        : "r"(a0), "r"(a1), "r"(a2), "r"(a3), "r"(b0), "r"(b1));
}
// fp16 mma, fp32 accumulate
__device__ __forceinline__ void mma16(float* c,
    uint32_t a0, uint32_t a1, uint32_t a2, uint32_t a3,
    uint32_t b0, uint32_t b1)
{
    asm volatile(
        "mma.sync.aligned.m16n8k16.row.col.f32.f16.f16.f32 "
        "{%0,%1,%2,%3},{%4,%5,%6,%7},{%8,%9},{%0,%1,%2,%3};"
        : "+f"(c[0]), "+f"(c[1]), "+f"(c[2]), "+f"(c[3])
        : "r"(a0), "r"(a1), "r"(a2), "r"(a3), "r"(b0), "r"(b1));
}

// -------------------- fp32 -> fp16 conversion --------------------
struct CvtArgs {
    const float* src[7];
    __half* dst[7];
    int bstart[8];     // block-range prefix (2048 elems per block)
};

__global__ __launch_bounds__(256) void cvt_f16(CvtArgs a)
{
    int bid = blockIdx.x, s = 0;
#pragma unroll
    for (int i = 1; i < 7; i++) if (bid >= a.bstart[i]) s = i;
    int off = (bid - a.bstart[s]) * 2048 + threadIdx.x * 8;
    float4 v0 = *reinterpret_cast<const float4*>(a.src[s] + off);
    float4 v1 = *reinterpret_cast<const float4*>(a.src[s] + off + 4);
    __half2 h0 = __floats2half2_rn(v0.x, v0.y);
    __half2 h1 = __floats2half2_rn(v0.z, v0.w);
    __half2 h2 = __floats2half2_rn(v1.x, v1.y);
    __half2 h3 = __floats2half2_rn(v1.z, v1.w);
    uint4 o;
    o.x = *reinterpret_cast<uint32_t*>(&h0);
    o.y = *reinterpret_cast<uint32_t*>(&h1);
    o.z = *reinterpret_cast<uint32_t*>(&h2);
    o.w = *reinterpret_cast<uint32_t*>(&h3);
    *reinterpret_cast<uint4*>(a.dst[s] + off) = o;
}

// -------------------- fp16 GEMM (segmented): C = A @ W^T + bias --------------------
// CTA tile 128x128, BK=32 fp16, double-buffered cp.async, 256 threads = 8 warps
// (4M x 2N), warp tile 32x64 via m16n8k16. smem stride 40 fp16 (conflict-free).
struct GemmSeg {
    const __half* A; const __half* W;
    const float* bias; const float* residual;
    void* C; int outHalf; int tileStart;
};
struct GemmArgs { GemmSeg seg[3]; int nseg; };

__global__ __launch_bounds__(256) void gemm_f16(GemmArgs ga)
{
    __shared__ __align__(16) uint32_t gsm[4 * 128 * 20];   // As0,As1,Bs0,Bs1

    const int y = blockIdx.y;
    int si = 0;
#pragma unroll
    for (int i = 1; i < 3; i++) if (i < ga.nseg && y >= ga.seg[i].tileStart) si = i;
    const GemmSeg sg = ga.seg[si];

    const int t = threadIdx.x, lane = t & 31, warp = t >> 5;
    const int g = lane >> 2, tg = lane & 3;
    const int wm = warp & 3, wn = warp >> 2;
    const int rowBase = (y - sg.tileStart) * 128, colBase = blockIdx.x * 128;
    const uint32_t smb = smaddr(gsm);

    auto loadStage = [&](int buf, int k0) {
#pragma unroll
        for (int i = 0; i < 2; i++) {
            int id = t + 256 * i;
            int r = id >> 2, c = (id & 3) * 8;
            cp16(smb + (uint32_t)(buf * 10240 + r * 80 + c * 2),
                 sg.A + (size_t)(rowBase + r) * HH + k0 + c);
            cp16(smb + (uint32_t)(20480 + buf * 10240 + r * 80 + c * 2),
                 sg.W + (size_t)(colBase + r) * HH + k0 + c);
        }
    };

    loadStage(0, 0);
    cp_commit();

    float acc[2][8][4] = {};
    const int nst = HH / 32;

    for (int s = 0; s < nst; s++) {
        cp_wait0();
        __syncthreads();
        if (s + 1 < nst) { loadStage((s + 1) & 1, (s + 1) * 32); cp_commit(); }

        const uint32_t* Ac = gsm + (s & 1) * 2560;
        const uint32_t* Bc = gsm + 5120 + (s & 1) * 2560;

#pragma unroll
        for (int k16 = 0; k16 < 2; k16++) {
            uint32_t a[2][4];
#pragma unroll
            for (int mi = 0; mi < 2; mi++) {
                int r = wm * 32 + mi * 16 + g;
                a[mi][0] = Ac[r * 20 + k16 * 8 + tg];
                a[mi][1] = Ac[(r + 8) * 20 + k16 * 8 + tg];
                a[mi][2] = Ac[r * 20 + k16 * 8 + 4 + tg];
                a[mi][3] = Ac[(r + 8) * 20 + k16 * 8 + 4 + tg];
            }
#pragma unroll
            for (int ni = 0; ni < 8; ni++) {
                int n = wn * 64 + ni * 8 + g;
                uint32_t b0 = Bc[n * 20 + k16 * 8 + tg];
                uint32_t b1 = Bc[n * 20 + k16 * 8 + 4 + tg];
                mma16(acc[0][ni], a[0][0], a[0][1], a[0][2], a[0][3], b0, b1);
                mma16(acc[1][ni], a[1][0], a[1][1], a[1][2], a[1][3], b0, b1);
            }
        }
    }

#pragma unroll
    for (int mi = 0; mi < 2; mi++) {
#pragma unroll
        for (int ni = 0; ni < 8; ni++) {
            int r = rowBase + wm * 32 + mi * 16 + g;
            int c = colBase + wn * 64 + ni * 8 + tg * 2;
            float b0 = sg.bias[c], b1 = sg.bias[c + 1];
            float v0 = acc[mi][ni][0] + b0, v1 = acc[mi][ni][1] + b1;
            float v2 = acc[mi][ni][2] + b0, v3 = acc[mi][ni][3] + b1;
            if (sg.outHalf) {
                __half* Ch = (__half*)sg.C;
                *reinterpret_cast<__half2*>(Ch + (size_t)r * HH + c) = __floats2half2_rn(v0, v1);
                *reinterpret_cast<__half2*>(Ch + (size_t)(r + 8) * HH + c) = __floats2half2_rn(v2, v3);
            } else {
                float* Cf = (float*)sg.C;
                if (sg.residual) {
                    float2 r0 = *reinterpret_cast<const float2*>(sg.residual + (size_t)r * HH + c);
                    float2 r1 = *reinterpret_cast<const float2*>(sg.residual + (size_t)(r + 8) * HH + c);
                    v0 += r0.x; v1 += r0.y; v2 += r1.x; v3 += r1.y;
                }
                *reinterpret_cast<float2*>(Cf + (size_t)r * HH + c) = make_float2(v0, v1);
                *reinterpret_cast<float2*>(Cf + (size_t)(r + 8) * HH + c) = make_float2(v2, v3);
            }
        }
    }
}

// -------------------- Flash attention v6: fp16 QK^T + tf32 PV --------------------
// CTA: 128 q-rows of one (b,h), 128 threads = 4 warps; warp = 32 rows x 64 cols.
// Q,K fp16 (m16n8k16), V fp32 + P fp32 via tf32 mma (unchanged, proven).
#define K16W (64 * 36)          // words per fp16 K stage (stride 36 words/row)
#define VSTW (64 * 72)          // words per fp32 V stage
#define AW_K 0
#define AW_V (2 * K16W)
#define AW_P (2 * K16W + 2 * VSTW)
#define A2_WORDS (AW_P + 128 * 68)
#define A2_BYTES (A2_WORDS * 4)     // 90112 -> 2 CTAs/SM

__global__ __launch_bounds__(128, 2) void attn_f16(
    const __half* __restrict__ Q, const __half* __restrict__ K,
    const float* __restrict__ V, const int* __restrict__ mask,
    __half* __restrict__ ctx)
{
    extern __shared__ __align__(16) uint32_t sh[];
    uint32_t* Kw = sh + AW_K;
    uint32_t* Vw = sh + AW_V;
    float*    Ps = reinterpret_cast<float*>(sh + AW_P);
    const uint32_t* Pu = sh + AW_P;

    const int q0 = blockIdx.x * 128, h = blockIdx.y, b = blockIdx.z;
    const int t = threadIdx.x, lane = t & 31, warp = t >> 5;
    const int g = lane >> 2, tg = lane & 3;
    const int wbase = warp * 32;

    const uint32_t smK = smaddr(Kw), smV = smaddr(Vw), smP = smaddr(Ps);

    // stage Q (fp16) into the P region: 128 rows x 64 halves, stride 144B
#pragma unroll
    for (int i = 0; i < 8; i++) {
        int id = t + 128 * i;
        int r = id >> 3, c = id & 7;
        cp16(smP + (uint32_t)(r * 144 + c * 16),
             Q + (size_t)(b * LQ + q0 + r) * HH + h * HD + c * 8);
    }
    auto loadKV = [&](int s, int k0) {
#pragma unroll
        for (int i = 0; i < 4; i++) {        // K fp16: 64 rows x 128B
            int id = t + 128 * i;
            int r = id >> 3, c = id & 7;
            cp16(smK + (uint32_t)(s * K16W * 4 + r * 144 + c * 16),
                 K + (size_t)(b * LK + k0 + r) * HH + h * HD + c * 8);
        }
#pragma unroll
        for (int i = 0; i < 8; i++) {        // V fp32: 64 rows x 256B
            int id = t + 128 * i;
            int r = id >> 4, c = id & 15;
            cp16(smV + (uint32_t)(s * VSTW * 4 + r * 288 + c * 16),
                 V + (size_t)(b * LK + k0 + r) * HH + h * HD + c * 4);
        }
    };
    loadKV(0, 0);
    cp_commit();
    cp_wait0();
    __syncthreads();

    // Q fragments (fp16 pairs) -> registers: [rt][k16][4]
    uint32_t qf[2][4][4];
#pragma unroll
    for (int rt = 0; rt < 2; rt++) {
        int r0 = wbase + rt * 16 + g, r1 = r0 + 8;
#pragma unroll
        for (int k16 = 0; k16 < 4; k16++) {
            qf[rt][k16][0] = Pu[r0 * 36 + k16 * 8 + tg];
            qf[rt][k16][1] = Pu[r1 * 36 + k16 * 8 + tg];
            qf[rt][k16][2] = Pu[r0 * 36 + k16 * 8 + 4 + tg];
            qf[rt][k16][3] = Pu[r1 * 36 + k16 * 8 + 4 + tg];
        }
    }
    __syncthreads();    // P region now free

    float acc[2][8][4] = {};
    float m0[2] = {-1e30f, -1e30f}, m1[2] = {-1e30f, -1e30f};
    float l0[2] = {0.f, 0.f}, l1[2] = {0.f, 0.f};
    const int* mbase = mask + (size_t)(b * LQ + q0) * LK;
    const int NT = LK / 64;

    for (int kt = 0; kt < NT; kt++) {
        if (kt + 1 < NT) { loadKV((kt + 1) & 1, (kt + 1) * 64); cp_commit(); }

        const uint32_t* Kc = Kw + (kt & 1) * K16W;
        const uint32_t* Vc = Vw + (kt & 1) * VSTW;

#pragma unroll
        for (int rt = 0; rt < 2; rt++) {
            const int r0 = wbase + rt * 16 + g, r1 = r0 + 8;

            int2 mk0[8], mk1[8];
#pragma unroll
            for (int ni = 0; ni < 8; ni++) {
                int c = ni * 8 + tg * 2;
                mk0[ni] = *reinterpret_cast<const int2*>(mbase + (size_t)r0 * LK + kt * 64 + c);
                mk1[ni] = *reinterpret_cast<const int2*>(mbase + (size_t)r1 * LK + kt * 64 + c);
            }

            // S = Q K^T (fp16 m16n8k16): 4 k16-steps
            float s[8][4] = {};
#pragma unroll
            for (int k16 = 0; k16 < 4; k16++) {
#pragma unroll
                for (int ni = 0; ni < 8; ni++) {
                    int n = ni * 8 + g;
                    uint32_t b0 = Kc[n * 36 + k16 * 8 + tg];
                    uint32_t b1 = Kc[n * 36 + k16 * 8 + 4 + tg];
                    mma16(s[ni], qf[rt][k16][0], qf[rt][k16][1],
                          qf[rt][k16][2], qf[rt][k16][3], b0, b1);
                }
            }

            float mx0 = m0[rt], mx1 = m1[rt];
#pragma unroll
            for (int ni = 0; ni < 8; ni++) {
                s[ni][0] = (mk0[ni].x == 0) ? -1e9f : s[ni][0] * 0.125f;
                s[ni][1] = (mk0[ni].y == 0) ? -1e9f : s[ni][1] * 0.125f;
                s[ni][2] = (mk1[ni].x == 0) ? -1e9f : s[ni][2] * 0.125f;
                s[ni][3] = (mk1[ni].y == 0) ? -1e9f : s[ni][3] * 0.125f;
                mx0 = fmaxf(mx0, fmaxf(s[ni][0], s[ni][1]));
                mx1 = fmaxf(mx1, fmaxf(s[ni][2], s[ni][3]));
            }
            mx0 = fmaxf(mx0, __shfl_xor_sync(0xffffffff, mx0, 1));
            mx0 = fmaxf(mx0, __shfl_xor_sync(0xffffffff, mx0, 2));
            mx1 = fmaxf(mx1, __shfl_xor_sync(0xffffffff, mx1, 1));
            mx1 = fmaxf(mx1, __shfl_xor_sync(0xffffffff, mx1, 2));

            float al0 = __expf(m0[rt] - mx0), al1 = __expf(m1[rt] - mx1);
            float ls0 = 0.f, ls1 = 0.f;
#pragma unroll
            for (int ni = 0; ni < 8; ni++) {
                s[ni][0] = __expf(s[ni][0] - mx0);
                s[ni][1] = __expf(s[ni][1] - mx0);
                s[ni][2] = __expf(s[ni][2] - mx1);
                s[ni][3] = __expf(s[ni][3] - mx1);
                ls0 += s[ni][0] + s[ni][1];
                ls1 += s[ni][2] + s[ni][3];
            }
            ls0 += __shfl_xor_sync(0xffffffff, ls0, 1);
            ls0 += __shfl_xor_sync(0xffffffff, ls0, 2);
            ls1 += __shfl_xor_sync(0xffffffff, ls1, 1);
            ls1 += __shfl_xor_sync(0xffffffff, ls1, 2);
            l0[rt] = l0[rt] * al0 + ls0;  m0[rt] = mx0;
            l1[rt] = l1[rt] * al1 + ls1;  m1[rt] = mx1;

#pragma unroll
            for (int ni = 0; ni < 8; ni++) {
                acc[rt][ni][0] *= al0; acc[rt][ni][1] *= al0;
                acc[rt][ni][2] *= al1; acc[rt][ni][3] *= al1;
                int c = ni * 8 + tg * 2;
                *reinterpret_cast<float2*>(&Ps[r0 * 68 + c]) = make_float2(s[ni][0], s[ni][1]);
                *reinterpret_cast<float2*>(&Ps[r1 * 68 + c]) = make_float2(s[ni][2], s[ni][3]);
            }
        }
        __syncwarp();

        // O += P @ V  (tf32; V fp32 [j][d] stride 72, B-frags reused by both rt)
#pragma unroll
        for (int kc = 0; kc < 8; kc++) {
            uint32_t a[2][4];
#pragma unroll
            for (int rt = 0; rt < 2; rt++) {
                int r0 = wbase + rt * 16 + g, r1 = r0 + 8;
                a[rt][0] = Pu[r0 * 68 + kc * 8 + tg];
                a[rt][1] = Pu[r1 * 68 + kc * 8 + tg];
                a[rt][2] = Pu[r0 * 68 + kc * 8 + 4 + tg];
                a[rt][3] = Pu[r1 * 68 + kc * 8 + 4 + tg];
            }
#pragma unroll
            for (int ni = 0; ni < 8; ni++) {
                int dn = ni * 8 + g;
                uint32_t b0 = Vc[(kc * 8 + tg) * 72 + dn];
                uint32_t b1 = Vc[(kc * 8 + 4 + tg) * 72 + dn];
                mma8(acc[0][ni], a[0][0], a[0][1], a[0][2], a[0][3], b0, b1);
                mma8(acc[1][ni], a[1][0], a[1][1], a[1][2], a[1][3], b0, b1);
            }
        }

        cp_wait0();
        __syncthreads();
    }

    // epilogue: ctx fp16
#pragma unroll
    for (int rt = 0; rt < 2; rt++) {
        int r0 = wbase + rt * 16 + g, r1 = r0 + 8;
        float inv0 = 1.f / l0[rt], inv1 = 1.f / l1[rt];
#pragma unroll
        for (int ni = 0; ni < 8; ni++) {
            int c = ni * 8 + tg * 2;
            size_t o0 = (size_t)(b * LQ + q0 + r0) * HH + h * HD + c;
            size_t o1 = (size_t)(b * LQ + q0 + r1) * HH + h * HD + c;
            *reinterpret_cast<__half2*>(ctx + o0) =
                __floats2half2_rn(acc[rt][ni][0] * inv0, acc[rt][ni][1] * inv0);
            *reinterpret_cast<__half2*>(ctx + o1) =
                __floats2half2_rn(acc[rt][ni][2] * inv1, acc[rt][ni][3] * inv1);
        }
    }
}

// -------------------- LayerNorm --------------------
__device__ __forceinline__ float block_reduce_sum(float v)
{
    __shared__ float red[8];
    __shared__ float tot;
    __syncthreads();
#pragma unroll
    for (int o = 16; o > 0; o >>= 1) v += __shfl_xor_sync(0xffffffff, v, o);
    int w = threadIdx.x >> 5;
    if ((threadIdx.x & 31) == 0) red[w] = v;
    __syncthreads();
    if (threadIdx.x < 32) {
        float r = (threadIdx.x < 8) ? red[threadIdx.x] : 0.f;
#pragma unroll
        for (int o = 4; o > 0; o >>= 1) r += __shfl_xor_sync(0xffffffff, r, o);
        if (threadIdx.x == 0) tot = r;
    }
    __syncthreads();
    return tot;
}

__global__ __launch_bounds__(256) void ln_kernel(
    const float* __restrict__ X, const float* __restrict__ g,
    const float* __restrict__ bta, float* __restrict__ out)
{
    int row = blockIdx.x;
    const float4 x4 = reinterpret_cast<const float4*>(X + (size_t)row * HH)[threadIdx.x];
    float v[4] = {x4.x, x4.y, x4.z, x4.w};
    float s = v[0] + v[1] + v[2] + v[3];
    float mean = block_reduce_sum(s) * (1.f / (float)HH);
    float d2 = 0.f;
#pragma unroll
    for (int j = 0; j < 4; j++) { float d = v[j] - mean; d2 += d * d; }
    float var = block_reduce_sum(d2) * (1.f / (float)HH);
    float rstd = rsqrtf(var + EPS);
    float4 g4 = reinterpret_cast<const float4*>(g)[threadIdx.x];
    float4 b4 = reinterpret_cast<const float4*>(bta)[threadIdx.x];
    float4 o;
    o.x = (v[0] - mean) * rstd * g4.x + b4.x;
    o.y = (v[1] - mean) * rstd * g4.y + b4.y;
    o.z = (v[2] - mean) * rstd * g4.z + b4.z;
    o.w = (v[3] - mean) * rstd * g4.w + b4.w;
    reinterpret_cast<float4*>(out + (size_t)row * HH)[threadIdx.x] = o;
}

// -------------------- launch --------------------
extern "C" void kernel_launch(void* const* d_in, const int* in_sizes, int n_in,
                              void* d_out, int out_size)
{
    const float* query = (const float*)d_in[0];
    const float* key   = (const float*)d_in[1];
    const float* value = (const float*)d_in[2];
    const int*   mask  = (const int*)d_in[3];
    const float* bq = (const float*)d_in[5];
    const float* bk = (const float*)d_in[7];
    const float* bv = (const float*)d_in[9];
    const float* bo = (const float*)d_in[11];
    const float* ln_g = (const float*)d_in[12];
    const float* ln_b = (const float*)d_in[13];
    float* out = (float*)d_out;

    __half *pq16, *pk16, *pv16, *pwq, *pwk, *pwv, *pwo, *pQ16, *pK16, *pctx;
    float *pV, *pX;
    cudaGetSymbolAddress((void**)&pq16, c_q16);
    cudaGetSymbolAddress((void**)&pk16, c_k16);
    cudaGetSymbolAddress((void**)&pv16, c_v16);
    cudaGetSymbolAddress((void**)&pwq, w16q);
    cudaGetSymbolAddress((void**)&pwk, w16k);
    cudaGetSymbolAddress((void**)&pwv, w16v);
    cudaGetSymbolAddress((void**)&pwo, w16o);
    cudaGetSymbolAddress((void**)&pQ16, g_Q16);
    cudaGetSymbolAddress((void**)&pK16, g_K16);
    cudaGetSymbolAddress((void**)&pV, g_V);
    cudaGetSymbolAddress((void**)&pctx, g_ctx16);
    cudaGetSymbolAddress((void**)&pX, g_x);

    cudaFuncSetAttribute(attn_f16,
                         cudaFuncAttributeMaxDynamicSharedMemorySize, A2_BYTES);

    // 1) convert inputs + weights to fp16
    CvtArgs ca;
    ca.src[0] = query; ca.dst[0] = pq16;   // 2M elems -> 1024 blocks
    ca.src[1] = key;   ca.dst[1] = pk16;   // 4M -> 2048
    ca.src[2] = value; ca.dst[2] = pv16;   // 4M -> 2048
    ca.src[3] = (const float*)d_in[4];  ca.dst[3] = pwq;   // 1M -> 512
    ca.src[4] = (const float*)d_in[6];  ca.dst[4] = pwk;
    ca.src[5] = (const float*)d_in[8];  ca.dst[5] = pwv;
    ca.src[6] = (const float*)d_in[10]; ca.dst[6] = pwo;
    int bs[8] = {0, 1024, 3072, 5120, 5632, 6144, 6656, 7168};
    for (int i = 0; i < 8; i++) ca.bstart[i] = bs[i];
    cvt_f16<<<7168, 256>>>(ca);

    // 2) fused Q/K/V projections (fp16 mma)
    GemmArgs qa;
    qa.nseg = 3;
    qa.seg[0] = {pq16, pwq, bq, nullptr, (void*)pQ16, 1, 0};
    qa.seg[1] = {pk16, pwk, bk, nullptr, (void*)pK16, 1, 16};
    qa.seg[2] = {pv16, pwv, bv, nullptr, (void*)pV,   0, 48};
    gemm_f16<<<dim3(HH / 128, 80), 256>>>(qa);

    // 3) attention
    attn_f16<<<dim3(LQ / 128, NH, BB), 128, A2_BYTES>>>(pQ16, pK16, pV, mask, pctx);

    // 4) output projection + residual
    GemmArgs oa;
    oa.nseg = 1;
    oa.seg[0] = {pctx, pwo, bo, query, (void*)pX, 0, 0};
    oa.seg[1] = oa.seg[0];
    oa.seg[2] = oa.seg[0];
    gemm_f16<<<dim3(HH / 128, 16), 256>>>(oa);

    // 5) layernorm
    ln_kernel<<<BB * LQ, 256>>>(pX, ln_g, ln_b, out);
}

// round 9
// speedup vs baseline: 6.0610x; 1.1799x over previous
#include <cuda_runtime.h>
#include <cuda_fp16.h>
#include <math.h>
#include <stdint.h>

// Problem constants (fixed shapes)
#define BB   2
#define LQ   1024
#define LK   2048
#define HH   1024
#define NH   16
#define HD   64
#define EPS  1e-5f

// -------------------- scratch --------------------
__device__ __align__(256) __half c_q16[BB * LQ * HH];
__device__ __align__(256) __half c_k16[BB * LK * HH];
__device__ __align__(256) __half c_v16[BB * LK * HH];
__device__ __align__(256) __half w16q[HH * HH];
__device__ __align__(256) __half w16k[HH * HH];
__device__ __align__(256) __half w16v[HH * HH];
__device__ __align__(256) __half w16o[HH * HH];
__device__ __align__(256) __half g_Q16[BB * LQ * HH];
__device__ __align__(256) __half g_K16[BB * LK * HH];
__device__ __align__(256) __half g_V16[BB * LK * HH];
__device__ __align__(256) __half g_ctx16[BB * LQ * HH];
__device__ __align__(256) float  g_x[BB * LQ * HH];

// -------------------- helpers --------------------
__device__ __forceinline__ uint32_t smaddr(const void* p) {
    return (uint32_t)__cvta_generic_to_shared(p);
}
__device__ __forceinline__ void cp16(uint32_t dst, const void* src) {
    asm volatile("cp.async.cg.shared.global [%0], [%1], 16;" :: "r"(dst), "l"(src));
}
__device__ __forceinline__ void cp_commit() {
    asm volatile("cp.async.commit_group;");
}
__device__ __forceinline__ void cp_wait0() {
    asm volatile("cp.async.wait_group 0;");
}
__device__ __forceinline__ void mma16(float* c,
    uint32_t a0, uint32_t a1, uint32_t a2, uint32_t a3,
    uint32_t b0, uint32_t b1)
{
    asm volatile(
        "mma.sync.aligned.m16n8k16.row.col.f32.f16.f16.f32 "
        "{%0,%1,%2,%3},{%4,%5,%6,%7},{%8,%9},{%0,%1,%2,%3};"
        : "+f"(c[0]), "+f"(c[1]), "+f"(c[2]), "+f"(c[3])
        : "r"(a0), "r"(a1), "r"(a2), "r"(a3), "r"(b0), "r"(b1));
}
__device__ __forceinline__ void ldsm4(uint32_t& r0, uint32_t& r1, uint32_t& r2,
                                      uint32_t& r3, uint32_t a)
{
    asm volatile("ldmatrix.sync.aligned.m8n8.x4.shared.b16 {%0,%1,%2,%3}, [%4];"
                 : "=r"(r0), "=r"(r1), "=r"(r2), "=r"(r3) : "r"(a));
}
__device__ __forceinline__ void ldsm4t(uint32_t& r0, uint32_t& r1, uint32_t& r2,
                                       uint32_t& r3, uint32_t a)
{
    asm volatile("ldmatrix.sync.aligned.m8n8.x4.trans.shared.b16 {%0,%1,%2,%3}, [%4];"
                 : "=r"(r0), "=r"(r1), "=r"(r2), "=r"(r3) : "r"(a));
}
__device__ __forceinline__ uint32_t ph2(float x, float y) {
    __half2 h = __floats2half2_rn(x, y);
    return *reinterpret_cast<uint32_t*>(&h);
}

// -------------------- fp32 -> fp16 conversion --------------------
struct CvtArgs {
    const float* src[7];
    __half* dst[7];
    int bstart[8];
};

__global__ __launch_bounds__(256) void cvt_f16(CvtArgs a)
{
    int bid = blockIdx.x, s = 0;
#pragma unroll
    for (int i = 1; i < 7; i++) if (bid >= a.bstart[i]) s = i;
    int off = (bid - a.bstart[s]) * 2048 + threadIdx.x * 8;
    float4 v0 = *reinterpret_cast<const float4*>(a.src[s] + off);
    float4 v1 = *reinterpret_cast<const float4*>(a.src[s] + off + 4);
    __half2 h0 = __floats2half2_rn(v0.x, v0.y);
    __half2 h1 = __floats2half2_rn(v0.z, v0.w);
    __half2 h2 = __floats2half2_rn(v1.x, v1.y);
    __half2 h3 = __floats2half2_rn(v1.z, v1.w);
    uint4 o;
    o.x = *reinterpret_cast<uint32_t*>(&h0);
    o.y = *reinterpret_cast<uint32_t*>(&h1);
    o.z = *reinterpret_cast<uint32_t*>(&h2);
    o.w = *reinterpret_cast<uint32_t*>(&h3);
    *reinterpret_cast<uint4*>(a.dst[s] + off) = o;
}

// -------------------- fp16 GEMM (segmented): C = A @ W^T + bias --------------------
struct GemmSeg {
    const __half* A; const __half* W;
    const float* bias; const float* residual;
    void* C; int outHalf; int tileStart;
};
struct GemmArgs { GemmSeg seg[3]; int nseg; };

__global__ __launch_bounds__(256) void gemm_f16(GemmArgs ga)
{
    __shared__ __align__(16) uint32_t gsm[4 * 128 * 20];

    const int y = blockIdx.y;
    int si = 0;
#pragma unroll
    for (int i = 1; i < 3; i++) if (i < ga.nseg && y >= ga.seg[i].tileStart) si = i;
    const GemmSeg sg = ga.seg[si];

    const int t = threadIdx.x, lane = t & 31, warp = t >> 5;
    const int g = lane >> 2, tg = lane & 3;
    const int wm = warp & 3, wn = warp >> 2;
    const int rowBase = (y - sg.tileStart) * 128, colBase = blockIdx.x * 128;
    const uint32_t smb = smaddr(gsm);

    auto loadStage = [&](int buf, int k0) {
#pragma unroll
        for (int i = 0; i < 2; i++) {
            int id = t + 256 * i;
            int r = id >> 2, c = (id & 3) * 8;
            cp16(smb + (uint32_t)(buf * 10240 + r * 80 + c * 2),
                 sg.A + (size_t)(rowBase + r) * HH + k0 + c);
            cp16(smb + (uint32_t)(20480 + buf * 10240 + r * 80 + c * 2),
                 sg.W + (size_t)(colBase + r) * HH + k0 + c);
        }
    };

    loadStage(0, 0);
    cp_commit();

    float acc[2][8][4] = {};
    const int nst = HH / 32;

    for (int s = 0; s < nst; s++) {
        cp_wait0();
        __syncthreads();
        if (s + 1 < nst) { loadStage((s + 1) & 1, (s + 1) * 32); cp_commit(); }

        const uint32_t* Ac = gsm + (s & 1) * 2560;
        const uint32_t* Bc = gsm + 5120 + (s & 1) * 2560;

#pragma unroll
        for (int k16 = 0; k16 < 2; k16++) {
            uint32_t a[2][4];
#pragma unroll
            for (int mi = 0; mi < 2; mi++) {
                int r = wm * 32 + mi * 16 + g;
                a[mi][0] = Ac[r * 20 + k16 * 8 + tg];
                a[mi][1] = Ac[(r + 8) * 20 + k16 * 8 + tg];
                a[mi][2] = Ac[r * 20 + k16 * 8 + 4 + tg];
                a[mi][3] = Ac[(r + 8) * 20 + k16 * 8 + 4 + tg];
            }
#pragma unroll
            for (int ni = 0; ni < 8; ni++) {
                int n = wn * 64 + ni * 8 + g;
                uint32_t b0 = Bc[n * 20 + k16 * 8 + tg];
                uint32_t b1 = Bc[n * 20 + k16 * 8 + 4 + tg];
                mma16(acc[0][ni], a[0][0], a[0][1], a[0][2], a[0][3], b0, b1);
                mma16(acc[1][ni], a[1][0], a[1][1], a[1][2], a[1][3], b0, b1);
            }
        }
    }

#pragma unroll
    for (int mi = 0; mi < 2; mi++) {
#pragma unroll
        for (int ni = 0; ni < 8; ni++) {
            int r = rowBase + wm * 32 + mi * 16 + g;
            int c = colBase + wn * 64 + ni * 8 + tg * 2;
            float b0 = sg.bias[c], b1 = sg.bias[c + 1];
            float v0 = acc[mi][ni][0] + b0, v1 = acc[mi][ni][1] + b1;
            float v2 = acc[mi][ni][2] + b0, v3 = acc[mi][ni][3] + b1;
            if (sg.outHalf) {
                __half* Ch = (__half*)sg.C;
                *reinterpret_cast<__half2*>(Ch + (size_t)r * HH + c) = __floats2half2_rn(v0, v1);
                *reinterpret_cast<__half2*>(Ch + (size_t)(r + 8) * HH + c) = __floats2half2_rn(v2, v3);
            } else {
                float* Cf = (float*)sg.C;
                if (sg.residual) {
                    float2 r0 = *reinterpret_cast<const float2*>(sg.residual + (size_t)r * HH + c);
                    float2 r1 = *reinterpret_cast<const float2*>(sg.residual + (size_t)(r + 8) * HH + c);
                    v0 += r0.x; v1 += r0.y; v2 += r1.x; v3 += r1.y;
                }
                *reinterpret_cast<float2*>(Cf + (size_t)r * HH + c) = make_float2(v0, v1);
                *reinterpret_cast<float2*>(Cf + (size_t)(r + 8) * HH + c) = make_float2(v2, v3);
            }
        }
    }
}

// -------------------- Flash attention v7: full fp16, ldmatrix, register P -------
// CTA: 128 q-rows of one (b,h), 128 threads = 4 warps; warp = 32 rows x 64 cols.
// K/V fp16 in smem (144B row stride: LDSM conflict-free). B-frags via ldmatrix
// (K non-trans, V trans). P stays in registers (QK output frag == PV A frag).
#define K16W 2304                    // words per K stage (64 rows x 36)
#define V16W 2304
#define A3_BYTES ((2 * K16W + 2 * V16W) * 4)   // 36864 bytes

__global__ __launch_bounds__(128, 2) void attn_f16(
    const __half* __restrict__ Q, const __half* __restrict__ K,
    const __half* __restrict__ V, const int* __restrict__ mask,
    __half* __restrict__ ctx)
{
    extern __shared__ __align__(16) uint32_t sh[];
    uint32_t* Kw = sh;
    uint32_t* Vw = sh + 2 * K16W;

    const int q0 = blockIdx.x * 128, h = blockIdx.y, b = blockIdx.z;
    const int t = threadIdx.x, lane = t & 31, warp = t >> 5;
    const int g = lane >> 2, tg = lane & 3;
    const int wbase = warp * 32;
    const int ti = lane >> 3, r8 = lane & 7;
    const int knRow = ((ti >> 1) << 3) + r8;   // K ldsm: row within 16-n block
    const int kCol  = ti & 1;                  // K ldsm: 16B chunk low/high
    const int vRow  = ((ti & 1) << 3) + r8;    // V ldsm: row within 16-j block
    const int vCol  = ti >> 1;

    const uint32_t smK = smaddr(Kw), smV = smaddr(Vw);

    // ---- stage Q (fp16) through the V region, extract fragments ----
#pragma unroll
    for (int i = 0; i < 8; i++) {
        int id = t + 128 * i;
        int r = id >> 3, c = id & 7;
        cp16(smV + (uint32_t)(r * 144 + c * 16),
             Q + (size_t)(b * LQ + q0 + r) * HH + h * HD + c * 8);
    }
    cp_commit(); cp_wait0(); __syncthreads();

    uint32_t qf[2][4][4];
#pragma unroll
    for (int rt = 0; rt < 2; rt++) {
        int r0 = wbase + rt * 16 + g, r1 = r0 + 8;
#pragma unroll
        for (int k16 = 0; k16 < 4; k16++) {
            qf[rt][k16][0] = Vw[r0 * 36 + k16 * 8 + tg];
            qf[rt][k16][1] = Vw[r1 * 36 + k16 * 8 + tg];
            qf[rt][k16][2] = Vw[r0 * 36 + k16 * 8 + 4 + tg];
            qf[rt][k16][3] = Vw[r1 * 36 + k16 * 8 + 4 + tg];
        }
    }
    __syncthreads();

    auto loadKV = [&](int s, int k0) {
#pragma unroll
        for (int i = 0; i < 4; i++) {
            int id = t + 128 * i;
            int r = id >> 3, c = id & 7;
            size_t gofs = (size_t)(b * LK + k0 + r) * HH + h * HD + c * 8;
            cp16(smK + (uint32_t)(s * K16W * 4 + r * 144 + c * 16), K + gofs);
            cp16(smV + (uint32_t)(s * V16W * 4 + r * 144 + c * 16), V + gofs);
        }
    };
    loadKV(0, 0);
    cp_commit(); cp_wait0(); __syncthreads();

    float acc[2][8][4] = {};
    float m0[2] = {-1e30f, -1e30f}, m1[2] = {-1e30f, -1e30f};
    float l0[2] = {0.f, 0.f}, l1[2] = {0.f, 0.f};
    const int* mbase = mask + (size_t)(b * LQ + q0) * LK;
    const int NT = LK / 64;

    for (int kt = 0; kt < NT; kt++) {
        if (kt + 1 < NT) { loadKV((kt + 1) & 1, (kt + 1) * 64); cp_commit(); }

        const uint32_t kcB = smK + (uint32_t)((kt & 1) * K16W * 4);
        const uint32_t vcB = smV + (uint32_t)((kt & 1) * V16W * 4);

        uint32_t pa[2][4][4];

#pragma unroll
        for (int rt = 0; rt < 2; rt++) {
            const int r0 = wbase + rt * 16 + g, r1 = r0 + 8;

            int2 mk0[8], mk1[8];
#pragma unroll
            for (int ni = 0; ni < 8; ni++) {
                int c = ni * 8 + tg * 2;
                mk0[ni] = *reinterpret_cast<const int2*>(mbase + (size_t)r0 * LK + kt * 64 + c);
                mk1[ni] = *reinterpret_cast<const int2*>(mbase + (size_t)r1 * LK + kt * 64 + c);
            }

            // S = Q K^T  (K B-frags via ldmatrix non-trans, conflict-free)
            float s[8][4] = {};
#pragma unroll
            for (int k16 = 0; k16 < 4; k16++) {
#pragma unroll
                for (int nip = 0; nip < 4; nip++) {
                    uint32_t b0, b1, b2, b3;
                    uint32_t addr = kcB + (uint32_t)((nip * 16 + knRow) * 144
                                                     + (k16 * 2 + kCol) * 16);
                    ldsm4(b0, b1, b2, b3, addr);
                    mma16(s[2 * nip], qf[rt][k16][0], qf[rt][k16][1],
                          qf[rt][k16][2], qf[rt][k16][3], b0, b1);
                    mma16(s[2 * nip + 1], qf[rt][k16][0], qf[rt][k16][1],
                          qf[rt][k16][2], qf[rt][k16][3], b2, b3);
                }
            }

            // mask + scale, row max (quad shuffle)
            float mx0 = m0[rt], mx1 = m1[rt];
#pragma unroll
            for (int ni = 0; ni < 8; ni++) {
                s[ni][0] = (mk0[ni].x == 0) ? -1e9f : s[ni][0] * 0.125f;
                s[ni][1] = (mk0[ni].y == 0) ? -1e9f : s[ni][1] * 0.125f;
                s[ni][2] = (mk1[ni].x == 0) ? -1e9f : s[ni][2] * 0.125f;
                s[ni][3] = (mk1[ni].y == 0) ? -1e9f : s[ni][3] * 0.125f;
                mx0 = fmaxf(mx0, fmaxf(s[ni][0], s[ni][1]));
                mx1 = fmaxf(mx1, fmaxf(s[ni][2], s[ni][3]));
            }
            mx0 = fmaxf(mx0, __shfl_xor_sync(0xffffffff, mx0, 1));
            mx0 = fmaxf(mx0, __shfl_xor_sync(0xffffffff, mx0, 2));
            mx1 = fmaxf(mx1, __shfl_xor_sync(0xffffffff, mx1, 1));
            mx1 = fmaxf(mx1, __shfl_xor_sync(0xffffffff, mx1, 2));

            float al0 = __expf(m0[rt] - mx0), al1 = __expf(m1[rt] - mx1);
            float ls0 = 0.f, ls1 = 0.f;
#pragma unroll
            for (int ni = 0; ni < 8; ni++) {
                s[ni][0] = __expf(s[ni][0] - mx0);
                s[ni][1] = __expf(s[ni][1] - mx0);
                s[ni][2] = __expf(s[ni][2] - mx1);
                s[ni][3] = __expf(s[ni][3] - mx1);
                ls0 += s[ni][0] + s[ni][1];
                ls1 += s[ni][2] + s[ni][3];
            }
            ls0 += __shfl_xor_sync(0xffffffff, ls0, 1);
            ls0 += __shfl_xor_sync(0xffffffff, ls0, 2);
            ls1 += __shfl_xor_sync(0xffffffff, ls1, 1);
            ls1 += __shfl_xor_sync(0xffffffff, ls1, 2);
            l0[rt] = l0[rt] * al0 + ls0;  m0[rt] = mx0;
            l1[rt] = l1[rt] * al1 + ls1;  m1[rt] = mx1;

            // rescale accumulator; pack P to fp16 A-fragments (registers only)
#pragma unroll
            for (int ni = 0; ni < 8; ni++) {
                acc[rt][ni][0] *= al0; acc[rt][ni][1] *= al0;
                acc[rt][ni][2] *= al1; acc[rt][ni][3] *= al1;
            }
#pragma unroll
            for (int k16 = 0; k16 < 4; k16++) {
                pa[rt][k16][0] = ph2(s[2 * k16][0], s[2 * k16][1]);
                pa[rt][k16][1] = ph2(s[2 * k16][2], s[2 * k16][3]);
                pa[rt][k16][2] = ph2(s[2 * k16 + 1][0], s[2 * k16 + 1][1]);
                pa[rt][k16][3] = ph2(s[2 * k16 + 1][2], s[2 * k16 + 1][3]);
            }
        }

        // O += P @ V  (V B-frags via ldmatrix.trans; shared across both rt)
#pragma unroll
        for (int k16 = 0; k16 < 4; k16++) {
#pragma unroll
            for (int nip = 0; nip < 4; nip++) {
                uint32_t b0, b1, b2, b3;
                uint32_t addr = vcB + (uint32_t)((k16 * 16 + vRow) * 144
                                                 + (nip * 2 + vCol) * 16);
                ldsm4t(b0, b1, b2, b3, addr);
                mma16(acc[0][2 * nip], pa[0][k16][0], pa[0][k16][1],
                      pa[0][k16][2], pa[0][k16][3], b0, b1);
                mma16(acc[0][2 * nip + 1], pa[0][k16][0], pa[0][k16][1],
                      pa[0][k16][2], pa[0][k16][3], b2, b3);
                mma16(acc[1][2 * nip], pa[1][k16][0], pa[1][k16][1],
                      pa[1][k16][2], pa[1][k16][3], b0, b1);
                mma16(acc[1][2 * nip + 1], pa[1][k16][0], pa[1][k16][1],
                      pa[1][k16][2], pa[1][k16][3], b2, b3);
            }
        }

        cp_wait0();
        __syncthreads();
    }

    // epilogue: ctx fp16
#pragma unroll
    for (int rt = 0; rt < 2; rt++) {
        int r0 = wbase + rt * 16 + g, r1 = r0 + 8;
        float inv0 = 1.f / l0[rt], inv1 = 1.f / l1[rt];
#pragma unroll
        for (int ni = 0; ni < 8; ni++) {
            int c = ni * 8 + tg * 2;
            size_t o0 = (size_t)(b * LQ + q0 + r0) * HH + h * HD + c;
            size_t o1 = (size_t)(b * LQ + q0 + r1) * HH + h * HD + c;
            *reinterpret_cast<__half2*>(ctx + o0) =
                __floats2half2_rn(acc[rt][ni][0] * inv0, acc[rt][ni][1] * inv0);
            *reinterpret_cast<__half2*>(ctx + o1) =
                __floats2half2_rn(acc[rt][ni][2] * inv1, acc[rt][ni][3] * inv1);
        }
    }
}

// -------------------- LayerNorm --------------------
__device__ __forceinline__ float block_reduce_sum(float v)
{
    __shared__ float red[8];
    __shared__ float tot;
    __syncthreads();
#pragma unroll
    for (int o = 16; o > 0; o >>= 1) v += __shfl_xor_sync(0xffffffff, v, o);
    int w = threadIdx.x >> 5;
    if ((threadIdx.x & 31) == 0) red[w] = v;
    __syncthreads();
    if (threadIdx.x < 32) {
        float r = (threadIdx.x < 8) ? red[threadIdx.x] : 0.f;
#pragma unroll
        for (int o = 4; o > 0; o >>= 1) r += __shfl_xor_sync(0xffffffff, r, o);
        if (threadIdx.x == 0) tot = r;
    }
    __syncthreads();
    return tot;
}

__global__ __launch_bounds__(256) void ln_kernel(
    const float* __restrict__ X, const float* __restrict__ g,
    const float* __restrict__ bta, float* __restrict__ out)
{
    int row = blockIdx.x;
    const float4 x4 = reinterpret_cast<const float4*>(X + (size_t)row * HH)[threadIdx.x];
    float v[4] = {x4.x, x4.y, x4.z, x4.w};
    float s = v[0] + v[1] + v[2] + v[3];
    float mean = block_reduce_sum(s) * (1.f / (float)HH);
    float d2 = 0.f;
#pragma unroll
    for (int j = 0; j < 4; j++) { float d = v[j] - mean; d2 += d * d; }
    float var = block_reduce_sum(d2) * (1.f / (float)HH);
    float rstd = rsqrtf(var + EPS);
    float4 g4 = reinterpret_cast<const float4*>(g)[threadIdx.x];
    float4 b4 = reinterpret_cast<const float4*>(bta)[threadIdx.x];
    float4 o;
    o.x = (v[0] - mean) * rstd * g4.x + b4.x;
    o.y = (v[1] - mean) * rstd * g4.y + b4.y;
    o.z = (v[2] - mean) * rstd * g4.z + b4.z;
    o.w = (v[3] - mean) * rstd * g4.w + b4.w;
    reinterpret_cast<float4*>(out + (size_t)row * HH)[threadIdx.x] = o;
}

// -------------------- launch --------------------
extern "C" void kernel_launch(void* const* d_in, const int* in_sizes, int n_in,
                              void* d_out, int out_size)
{
    const float* query = (const float*)d_in[0];
    const float* key   = (const float*)d_in[1];
    const float* value = (const float*)d_in[2];
    const int*   mask  = (const int*)d_in[3];
    const float* bq = (const float*)d_in[5];
    const float* bk = (const float*)d_in[7];
    const float* bv = (const float*)d_in[9];
    const float* bo = (const float*)d_in[11];
    const float* ln_g = (const float*)d_in[12];
    const float* ln_b = (const float*)d_in[13];
    float* out = (float*)d_out;

    __half *pq16, *pk16, *pv16, *pwq, *pwk, *pwv, *pwo, *pQ16, *pK16, *pV16, *pctx;
    float *pX;
    cudaGetSymbolAddress((void**)&pq16, c_q16);
    cudaGetSymbolAddress((void**)&pk16, c_k16);
    cudaGetSymbolAddress((void**)&pv16, c_v16);
    cudaGetSymbolAddress((void**)&pwq, w16q);
    cudaGetSymbolAddress((void**)&pwk, w16k);
    cudaGetSymbolAddress((void**)&pwv, w16v);
    cudaGetSymbolAddress((void**)&pwo, w16o);
    cudaGetSymbolAddress((void**)&pQ16, g_Q16);
    cudaGetSymbolAddress((void**)&pK16, g_K16);
    cudaGetSymbolAddress((void**)&pV16, g_V16);
    cudaGetSymbolAddress((void**)&pctx, g_ctx16);
    cudaGetSymbolAddress((void**)&pX, g_x);

    cudaFuncSetAttribute(attn_f16,
                         cudaFuncAttributeMaxDynamicSharedMemorySize, A3_BYTES);

    // 1) convert inputs + weights to fp16
    CvtArgs ca;
    ca.src[0] = query; ca.dst[0] = pq16;
    ca.src[1] = key;   ca.dst[1] = pk16;
    ca.src[2] = value; ca.dst[2] = pv16;
    ca.src[3] = (const float*)d_in[4];  ca.dst[3] = pwq;
    ca.src[4] = (const float*)d_in[6];  ca.dst[4] = pwk;
    ca.src[5] = (const float*)d_in[8];  ca.dst[5] = pwv;
    ca.src[6] = (const float*)d_in[10]; ca.dst[6] = pwo;
    int bs[8] = {0, 1024, 3072, 5120, 5632, 6144, 6656, 7168};
    for (int i = 0; i < 8; i++) ca.bstart[i] = bs[i];
    cvt_f16<<<7168, 256>>>(ca);

    // 2) fused Q/K/V projections (fp16 mma); V output fp16 now
    GemmArgs qa;
    qa.nseg = 3;
    qa.seg[0] = {pq16, pwq, bq, nullptr, (void*)pQ16, 1, 0};
    qa.seg[1] = {pk16, pwk, bk, nullptr, (void*)pK16, 1, 16};
    qa.seg[2] = {pv16, pwv, bv, nullptr, (void*)pV16, 1, 48};
    gemm_f16<<<dim3(HH / 128, 80), 256>>>(qa);

    // 3) attention (full fp16)
    attn_f16<<<dim3(LQ / 128, NH, BB), 128, A3_BYTES>>>(pQ16, pK16, pV16, mask, pctx);

    // 4) output projection + residual (fp32 out)
    GemmArgs oa;
    oa.nseg = 1;
    oa.seg[0] = {pctx, pwo, bo, query, (void*)pX, 0, 0};
    oa.seg[1] = oa.seg[0];
    oa.seg[2] = oa.seg[0];
    gemm_f16<<<dim3(HH / 128, 16), 256>>>(oa);

    // 5) layernorm
    ln_kernel<<<BB * LQ, 256>>>(pX, ln_g, ln_b, out);
}

// round 10
// speedup vs baseline: 6.3781x; 1.0523x over previous
#include <cuda_runtime.h>
#include <cuda_fp16.h>
#include <math.h>
#include <stdint.h>

// Problem constants (fixed shapes)
#define BB   2
#define LQ   1024
#define LK   2048
#define HH   1024
#define NH   16
#define HD   64
#define EPS  1e-5f

// -------------------- scratch --------------------
__device__ __align__(256) __half c_q16[BB * LQ * HH];
__device__ __align__(256) __half c_k16[BB * LK * HH];
__device__ __align__(256) __half c_v16[BB * LK * HH];
__device__ __align__(256) __half w16q[HH * HH];
__device__ __align__(256) __half w16k[HH * HH];
__device__ __align__(256) __half w16v[HH * HH];
__device__ __align__(256) __half w16o[HH * HH];
__device__ __align__(256) __half g_Q16[BB * LQ * HH];
__device__ __align__(256) __half g_K16[BB * LK * HH];
__device__ __align__(256) __half g_V16[BB * LK * HH];
__device__ __align__(256) __half g_ctx16[BB * LQ * HH];
__device__ __align__(256) float  g_x[BB * LQ * HH];

// -------------------- helpers --------------------
__device__ __forceinline__ uint32_t smaddr(const void* p) {
    return (uint32_t)__cvta_generic_to_shared(p);
}
__device__ __forceinline__ void cp16(uint32_t dst, const void* src) {
    asm volatile("cp.async.cg.shared.global [%0], [%1], 16;" :: "r"(dst), "l"(src));
}
__device__ __forceinline__ void cp_commit() {
    asm volatile("cp.async.commit_group;");
}
__device__ __forceinline__ void cp_wait0() {
    asm volatile("cp.async.wait_group 0;");
}
__device__ __forceinline__ void mma16(float* c,
    uint32_t a0, uint32_t a1, uint32_t a2, uint32_t a3,
    uint32_t b0, uint32_t b1)
{
    asm volatile(
        "mma.sync.aligned.m16n8k16.row.col.f32.f16.f16.f32 "
        "{%0,%1,%2,%3},{%4,%5,%6,%7},{%8,%9},{%0,%1,%2,%3};"
        : "+f"(c[0]), "+f"(c[1]), "+f"(c[2]), "+f"(c[3])
        : "r"(a0), "r"(a1), "r"(a2), "r"(a3), "r"(b0), "r"(b1));
}
__device__ __forceinline__ void ldsm4(uint32_t& r0, uint32_t& r1, uint32_t& r2,
                                      uint32_t& r3, uint32_t a)
{
    asm volatile("ldmatrix.sync.aligned.m8n8.x4.shared.b16 {%0,%1,%2,%3}, [%4];"
                 : "=r"(r0), "=r"(r1), "=r"(r2), "=r"(r3) : "r"(a));
}
__device__ __forceinline__ void ldsm4t(uint32_t& r0, uint32_t& r1, uint32_t& r2,
                                       uint32_t& r3, uint32_t a)
{
    asm volatile("ldmatrix.sync.aligned.m8n8.x4.trans.shared.b16 {%0,%1,%2,%3}, [%4];"
                 : "=r"(r0), "=r"(r1), "=r"(r2), "=r"(r3) : "r"(a));
}
__device__ __forceinline__ uint32_t ph2(float x, float y) {
    __half2 h = __floats2half2_rn(x, y);
    return *reinterpret_cast<uint32_t*>(&h);
}

// -------------------- fp32 -> fp16 conversion --------------------
struct CvtArgs {
    const float* src[7];
    __half* dst[7];
    int bstart[8];
};

__global__ __launch_bounds__(256) void cvt_f16(CvtArgs a)
{
    int bid = blockIdx.x, s = 0;
#pragma unroll
    for (int i = 1; i < 7; i++) if (bid >= a.bstart[i]) s = i;
    int off = (bid - a.bstart[s]) * 2048 + threadIdx.x * 8;
    float4 v0 = *reinterpret_cast<const float4*>(a.src[s] + off);
    float4 v1 = *reinterpret_cast<const float4*>(a.src[s] + off + 4);
    __half2 h0 = __floats2half2_rn(v0.x, v0.y);
    __half2 h1 = __floats2half2_rn(v0.z, v0.w);
    __half2 h2 = __floats2half2_rn(v1.x, v1.y);
    __half2 h3 = __floats2half2_rn(v1.z, v1.w);
    uint4 o;
    o.x = *reinterpret_cast<uint32_t*>(&h0);
    o.y = *reinterpret_cast<uint32_t*>(&h1);
    o.z = *reinterpret_cast<uint32_t*>(&h2);
    o.w = *reinterpret_cast<uint32_t*>(&h3);
    *reinterpret_cast<uint4*>(a.dst[s] + off) = o;
}

// -------------------- fp16 GEMM (templated N-tile): C = A @ W^T + bias ---------
// CTA tile 128(M) x NT(N), BK=32, double-buffered cp.async, 256 threads =
// 8 warps (4M x 2N), warp tile 32 x NT/2. launch_bounds(256,2) -> 2 CTAs/SM.
struct GemmSeg {
    const __half* A; const __half* W;
    const float* bias; const float* residual;
    void* C; int outHalf; int tileStart;
};
struct GemmArgs { GemmSeg seg[3]; int nseg; };

template<int NT>
__global__ __launch_bounds__(256, 2) void gemm_f16(GemmArgs ga)
{
    constexpr int NI = NT / 16;            // mma n-steps per warp
    __shared__ __align__(16) uint32_t Asm[2 * 128 * 20];
    __shared__ __align__(16) uint32_t Bsm[2 * NT * 20];

    const int y = blockIdx.y;
    int si = 0;
#pragma unroll
    for (int i = 1; i < 3; i++) if (i < ga.nseg && y >= ga.seg[i].tileStart) si = i;
    const GemmSeg sg = ga.seg[si];

    const int t = threadIdx.x, lane = t & 31, warp = t >> 5;
    const int g = lane >> 2, tg = lane & 3;
    const int wm = warp & 3, wn = warp >> 2;
    const int rowBase = (y - sg.tileStart) * 128, colBase = blockIdx.x * NT;
    const uint32_t smA = smaddr(Asm), smB = smaddr(Bsm);

    auto loadStage = [&](int buf, int k0) {
#pragma unroll
        for (int i = 0; i < 2; i++) {
            int id = t + 256 * i;
            int r = id >> 2, c = (id & 3) * 8;
            cp16(smA + (uint32_t)(buf * 10240 + r * 80 + c * 2),
                 sg.A + (size_t)(rowBase + r) * HH + k0 + c);
        }
#pragma unroll
        for (int i = 0; i < NT / 64; i++) {
            int id = t + 256 * i;
            int r = id >> 2, c = (id & 3) * 8;
            cp16(smB + (uint32_t)(buf * (NT * 80) + r * 80 + c * 2),
                 sg.W + (size_t)(colBase + r) * HH + k0 + c);
        }
    };

    loadStage(0, 0);
    cp_commit();

    float acc[2][NI][4] = {};
    const int nst = HH / 32;

    for (int s = 0; s < nst; s++) {
        cp_wait0();
        __syncthreads();
        if (s + 1 < nst) { loadStage((s + 1) & 1, (s + 1) * 32); cp_commit(); }

        const uint32_t* Ac = Asm + (s & 1) * 2560;
        const uint32_t* Bc = Bsm + (s & 1) * (NT * 20);

#pragma unroll
        for (int k16 = 0; k16 < 2; k16++) {
            uint32_t a[2][4];
#pragma unroll
            for (int mi = 0; mi < 2; mi++) {
                int r = wm * 32 + mi * 16 + g;
                a[mi][0] = Ac[r * 20 + k16 * 8 + tg];
                a[mi][1] = Ac[(r + 8) * 20 + k16 * 8 + tg];
                a[mi][2] = Ac[r * 20 + k16 * 8 + 4 + tg];
                a[mi][3] = Ac[(r + 8) * 20 + k16 * 8 + 4 + tg];
            }
#pragma unroll
            for (int ni = 0; ni < NI; ni++) {
                int n = wn * (NT / 2) + ni * 8 + g;
                uint32_t b0 = Bc[n * 20 + k16 * 8 + tg];
                uint32_t b1 = Bc[n * 20 + k16 * 8 + 4 + tg];
                mma16(acc[0][ni], a[0][0], a[0][1], a[0][2], a[0][3], b0, b1);
                mma16(acc[1][ni], a[1][0], a[1][1], a[1][2], a[1][3], b0, b1);
            }
        }
    }

#pragma unroll
    for (int mi = 0; mi < 2; mi++) {
#pragma unroll
        for (int ni = 0; ni < NI; ni++) {
            int r = rowBase + wm * 32 + mi * 16 + g;
            int c = colBase + wn * (NT / 2) + ni * 8 + tg * 2;
            float b0 = sg.bias[c], b1 = sg.bias[c + 1];
            float v0 = acc[mi][ni][0] + b0, v1 = acc[mi][ni][1] + b1;
            float v2 = acc[mi][ni][2] + b0, v3 = acc[mi][ni][3] + b1;
            if (sg.outHalf) {
                __half* Ch = (__half*)sg.C;
                *reinterpret_cast<__half2*>(Ch + (size_t)r * HH + c) = __floats2half2_rn(v0, v1);
                *reinterpret_cast<__half2*>(Ch + (size_t)(r + 8) * HH + c) = __floats2half2_rn(v2, v3);
            } else {
                float* Cf = (float*)sg.C;
                if (sg.residual) {
                    float2 r0 = *reinterpret_cast<const float2*>(sg.residual + (size_t)r * HH + c);
                    float2 r1 = *reinterpret_cast<const float2*>(sg.residual + (size_t)(r + 8) * HH + c);
                    v0 += r0.x; v1 += r0.y; v2 += r1.x; v3 += r1.y;
                }
                *reinterpret_cast<float2*>(Cf + (size_t)r * HH + c) = make_float2(v0, v1);
                *reinterpret_cast<float2*>(Cf + (size_t)(r + 8) * HH + c) = make_float2(v2, v3);
            }
        }
    }
}

// -------------------- Flash attention v8: 256 threads, ldsm, register P --------
// CTA: 128 q-rows of one (b,h), 256 threads = 8 warps; warp = 16 rows x 64 cols.
// K/V fp16 in smem (144B row stride), B-frags via ldmatrix, P in registers.
#define K16W 2304
#define V16W 2304
#define A3_BYTES ((2 * K16W + 2 * V16W) * 4)   // 36864 bytes -> 2 CTAs/SM

__global__ __launch_bounds__(256, 2) void attn_f16(
    const __half* __restrict__ Q, const __half* __restrict__ K,
    const __half* __restrict__ V, const int* __restrict__ mask,
    __half* __restrict__ ctx)
{
    extern __shared__ __align__(16) uint32_t sh[];
    uint32_t* Kw = sh;
    uint32_t* Vw = sh + 2 * K16W;

    const int q0 = blockIdx.x * 128, h = blockIdx.y, b = blockIdx.z;
    const int t = threadIdx.x, lane = t & 31, warp = t >> 5;
    const int g = lane >> 2, tg = lane & 3;
    const int wbase = warp * 16;
    const int ti = lane >> 3, r8 = lane & 7;
    const int knRow = ((ti >> 1) << 3) + r8;
    const int kCol  = ti & 1;
    const int vRow  = ((ti & 1) << 3) + r8;
    const int vCol  = ti >> 1;

    const uint32_t smK = smaddr(Kw), smV = smaddr(Vw);

    // stage Q through the V region, extract fragments
#pragma unroll
    for (int i = 0; i < 4; i++) {
        int id = t + 256 * i;
        int r = id >> 3, c = id & 7;
        cp16(smV + (uint32_t)(r * 144 + c * 16),
             Q + (size_t)(b * LQ + q0 + r) * HH + h * HD + c * 8);
    }
    cp_commit(); cp_wait0(); __syncthreads();

    uint32_t qf[4][4];
    {
        int r0 = wbase + g, r1 = r0 + 8;
#pragma unroll
        for (int k16 = 0; k16 < 4; k16++) {
            qf[k16][0] = Vw[r0 * 36 + k16 * 8 + tg];
            qf[k16][1] = Vw[r1 * 36 + k16 * 8 + tg];
            qf[k16][2] = Vw[r0 * 36 + k16 * 8 + 4 + tg];
            qf[k16][3] = Vw[r1 * 36 + k16 * 8 + 4 + tg];
        }
    }
    __syncthreads();

    auto loadKV = [&](int s, int k0) {
#pragma unroll
        for (int i = 0; i < 2; i++) {
            int id = t + 256 * i;
            int r = id >> 3, c = id & 7;
            size_t gofs = (size_t)(b * LK + k0 + r) * HH + h * HD + c * 8;
            cp16(smK + (uint32_t)(s * K16W * 4 + r * 144 + c * 16), K + gofs);
            cp16(smV + (uint32_t)(s * V16W * 4 + r * 144 + c * 16), V + gofs);
        }
    };
    loadKV(0, 0);
    cp_commit(); cp_wait0(); __syncthreads();

    float acc[8][4] = {};
    float m0 = -1e30f, m1 = -1e30f, l0 = 0.f, l1 = 0.f;
    const int* mbase = mask + (size_t)(b * LQ + q0) * LK;
    const int NT = LK / 64;
    const int r0 = wbase + g, r1 = r0 + 8;

    for (int kt = 0; kt < NT; kt++) {
        if (kt + 1 < NT) { loadKV((kt + 1) & 1, (kt + 1) * 64); cp_commit(); }

        const uint32_t kcB = smK + (uint32_t)((kt & 1) * K16W * 4);
        const uint32_t vcB = smV + (uint32_t)((kt & 1) * V16W * 4);

        int2 mk0[8], mk1[8];
#pragma unroll
        for (int ni = 0; ni < 8; ni++) {
            int c = ni * 8 + tg * 2;
            mk0[ni] = *reinterpret_cast<const int2*>(mbase + (size_t)r0 * LK + kt * 64 + c);
            mk1[ni] = *reinterpret_cast<const int2*>(mbase + (size_t)r1 * LK + kt * 64 + c);
        }

        // S = Q K^T
        float s[8][4] = {};
#pragma unroll
        for (int k16 = 0; k16 < 4; k16++) {
#pragma unroll
            for (int nip = 0; nip < 4; nip++) {
                uint32_t b0, b1, b2, b3;
                uint32_t addr = kcB + (uint32_t)((nip * 16 + knRow) * 144
                                                 + (k16 * 2 + kCol) * 16);
                ldsm4(b0, b1, b2, b3, addr);
                mma16(s[2 * nip], qf[k16][0], qf[k16][1], qf[k16][2], qf[k16][3], b0, b1);
                mma16(s[2 * nip + 1], qf[k16][0], qf[k16][1], qf[k16][2], qf[k16][3], b2, b3);
            }
        }

        // mask + scale, row max
        float mx0 = m0, mx1 = m1;
#pragma unroll
        for (int ni = 0; ni < 8; ni++) {
            s[ni][0] = (mk0[ni].x == 0) ? -1e9f : s[ni][0] * 0.125f;
            s[ni][1] = (mk0[ni].y == 0) ? -1e9f : s[ni][1] * 0.125f;
            s[ni][2] = (mk1[ni].x == 0) ? -1e9f : s[ni][2] * 0.125f;
            s[ni][3] = (mk1[ni].y == 0) ? -1e9f : s[ni][3] * 0.125f;
            mx0 = fmaxf(mx0, fmaxf(s[ni][0], s[ni][1]));
            mx1 = fmaxf(mx1, fmaxf(s[ni][2], s[ni][3]));
        }
        mx0 = fmaxf(mx0, __shfl_xor_sync(0xffffffff, mx0, 1));
        mx0 = fmaxf(mx0, __shfl_xor_sync(0xffffffff, mx0, 2));
        mx1 = fmaxf(mx1, __shfl_xor_sync(0xffffffff, mx1, 1));
        mx1 = fmaxf(mx1, __shfl_xor_sync(0xffffffff, mx1, 2));

        float al0 = __expf(m0 - mx0), al1 = __expf(m1 - mx1);
        float ls0 = 0.f, ls1 = 0.f;
#pragma unroll
        for (int ni = 0; ni < 8; ni++) {
            s[ni][0] = __expf(s[ni][0] - mx0);
            s[ni][1] = __expf(s[ni][1] - mx0);
            s[ni][2] = __expf(s[ni][2] - mx1);
            s[ni][3] = __expf(s[ni][3] - mx1);
            ls0 += s[ni][0] + s[ni][1];
            ls1 += s[ni][2] + s[ni][3];
        }
        ls0 += __shfl_xor_sync(0xffffffff, ls0, 1);
        ls0 += __shfl_xor_sync(0xffffffff, ls0, 2);
        ls1 += __shfl_xor_sync(0xffffffff, ls1, 1);
        ls1 += __shfl_xor_sync(0xffffffff, ls1, 2);
        l0 = l0 * al0 + ls0;  m0 = mx0;
        l1 = l1 * al1 + ls1;  m1 = mx1;

        // rescale accumulator; pack P to fp16 A-fragments (registers only)
        uint32_t pa[4][4];
#pragma unroll
        for (int ni = 0; ni < 8; ni++) {
            acc[ni][0] *= al0; acc[ni][1] *= al0;
            acc[ni][2] *= al1; acc[ni][3] *= al1;
        }
#pragma unroll
        for (int k16 = 0; k16 < 4; k16++) {
            pa[k16][0] = ph2(s[2 * k16][0], s[2 * k16][1]);
            pa[k16][1] = ph2(s[2 * k16][2], s[2 * k16][3]);
            pa[k16][2] = ph2(s[2 * k16 + 1][0], s[2 * k16 + 1][1]);
            pa[k16][3] = ph2(s[2 * k16 + 1][2], s[2 * k16 + 1][3]);
        }

        // O += P @ V
#pragma unroll
        for (int k16 = 0; k16 < 4; k16++) {
#pragma unroll
            for (int nip = 0; nip < 4; nip++) {
                uint32_t b0, b1, b2, b3;
                uint32_t addr = vcB + (uint32_t)((k16 * 16 + vRow) * 144
                                                 + (nip * 2 + vCol) * 16);
                ldsm4t(b0, b1, b2, b3, addr);
                mma16(acc[2 * nip], pa[k16][0], pa[k16][1], pa[k16][2], pa[k16][3], b0, b1);
                mma16(acc[2 * nip + 1], pa[k16][0], pa[k16][1], pa[k16][2], pa[k16][3], b2, b3);
            }
        }

        cp_wait0();
        __syncthreads();
    }

    // epilogue: ctx fp16
    {
        float inv0 = 1.f / l0, inv1 = 1.f / l1;
#pragma unroll
        for (int ni = 0; ni < 8; ni++) {
            int c = ni * 8 + tg * 2;
            size_t o0 = (size_t)(b * LQ + q0 + r0) * HH + h * HD + c;
            size_t o1 = (size_t)(b * LQ + q0 + r1) * HH + h * HD + c;
            *reinterpret_cast<__half2*>(ctx + o0) =
                __floats2half2_rn(acc[ni][0] * inv0, acc[ni][1] * inv0);
            *reinterpret_cast<__half2*>(ctx + o1) =
                __floats2half2_rn(acc[ni][2] * inv1, acc[ni][3] * inv1);
        }
    }
}

// -------------------- LayerNorm --------------------
__device__ __forceinline__ float block_reduce_sum(float v)
{
    __shared__ float red[8];
    __shared__ float tot;
    __syncthreads();
#pragma unroll
    for (int o = 16; o > 0; o >>= 1) v += __shfl_xor_sync(0xffffffff, v, o);
    int w = threadIdx.x >> 5;
    if ((threadIdx.x & 31) == 0) red[w] = v;
    __syncthreads();
    if (threadIdx.x < 32) {
        float r = (threadIdx.x < 8) ? red[threadIdx.x] : 0.f;
#pragma unroll
        for (int o = 4; o > 0; o >>= 1) r += __shfl_xor_sync(0xffffffff, r, o);
        if (threadIdx.x == 0) tot = r;
    }
    __syncthreads();
    return tot;
}

__global__ __launch_bounds__(256) void ln_kernel(
    const float* __restrict__ X, const float* __restrict__ g,
    const float* __restrict__ bta, float* __restrict__ out)
{
    int row = blockIdx.x;
    const float4 x4 = reinterpret_cast<const float4*>(X + (size_t)row * HH)[threadIdx.x];
    float v[4] = {x4.x, x4.y, x4.z, x4.w};
    float s = v[0] + v[1] + v[2] + v[3];
    float mean = block_reduce_sum(s) * (1.f / (float)HH);
    float d2 = 0.f;
#pragma unroll
    for (int j = 0; j < 4; j++) { float d = v[j] - mean; d2 += d * d; }
    float var = block_reduce_sum(d2) * (1.f / (float)HH);
    float rstd = rsqrtf(var + EPS);
    float4 g4 = reinterpret_cast<const float4*>(g)[threadIdx.x];
    float4 b4 = reinterpret_cast<const float4*>(bta)[threadIdx.x];
    float4 o;
    o.x = (v[0] - mean) * rstd * g4.x + b4.x;
    o.y = (v[1] - mean) * rstd * g4.y + b4.y;
    o.z = (v[2] - mean) * rstd * g4.z + b4.z;
    o.w = (v[3] - mean) * rstd * g4.w + b4.w;
    reinterpret_cast<float4*>(out + (size_t)row * HH)[threadIdx.x] = o;
}

// -------------------- launch --------------------
extern "C" void kernel_launch(void* const* d_in, const int* in_sizes, int n_in,
                              void* d_out, int out_size)
{
    const float* query = (const float*)d_in[0];
    const float* key   = (const float*)d_in[1];
    const float* value = (const float*)d_in[2];
    const int*   mask  = (const int*)d_in[3];
    const float* bq = (const float*)d_in[5];
    const float* bk = (const float*)d_in[7];
    const float* bv = (const float*)d_in[9];
    const float* bo = (const float*)d_in[11];
    const float* ln_g = (const float*)d_in[12];
    const float* ln_b = (const float*)d_in[13];
    float* out = (float*)d_out;

    __half *pq16, *pk16, *pv16, *pwq, *pwk, *pwv, *pwo, *pQ16, *pK16, *pV16, *pctx;
    float *pX;
    cudaGetSymbolAddress((void**)&pq16, c_q16);
    cudaGetSymbolAddress((void**)&pk16, c_k16);
    cudaGetSymbolAddress((void**)&pv16, c_v16);
    cudaGetSymbolAddress((void**)&pwq, w16q);
    cudaGetSymbolAddress((void**)&pwk, w16k);
    cudaGetSymbolAddress((void**)&pwv, w16v);
    cudaGetSymbolAddress((void**)&pwo, w16o);
    cudaGetSymbolAddress((void**)&pQ16, g_Q16);
    cudaGetSymbolAddress((void**)&pK16, g_K16);
    cudaGetSymbolAddress((void**)&pV16, g_V16);
    cudaGetSymbolAddress((void**)&pctx, g_ctx16);
    cudaGetSymbolAddress((void**)&pX, g_x);

    cudaFuncSetAttribute(attn_f16,
                         cudaFuncAttributeMaxDynamicSharedMemorySize, A3_BYTES);

    // 1) convert inputs + weights to fp16
    CvtArgs ca;
    ca.src[0] = query; ca.dst[0] = pq16;
    ca.src[1] = key;   ca.dst[1] = pk16;
    ca.src[2] = value; ca.dst[2] = pv16;
    ca.src[3] = (const float*)d_in[4];  ca.dst[3] = pwq;
    ca.src[4] = (const float*)d_in[6];  ca.dst[4] = pwk;
    ca.src[5] = (const float*)d_in[8];  ca.dst[5] = pwv;
    ca.src[6] = (const float*)d_in[10]; ca.dst[6] = pwo;
    int bs[8] = {0, 1024, 3072, 5120, 5632, 6144, 6656, 7168};
    for (int i = 0; i < 8; i++) ca.bstart[i] = bs[i];
    cvt_f16<<<7168, 256>>>(ca);

    // 2) fused Q/K/V projections (fp16 mma)
    GemmArgs qa;
    qa.nseg = 3;
    qa.seg[0] = {pq16, pwq, bq, nullptr, (void*)pQ16, 1, 0};
    qa.seg[1] = {pk16, pwk, bk, nullptr, (void*)pK16, 1, 16};
    qa.seg[2] = {pv16, pwv, bv, nullptr, (void*)pV16, 1, 48};
    gemm_f16<128><<<dim3(HH / 128, 80), 256>>>(qa);

    // 3) attention
    attn_f16<<<dim3(LQ / 128, NH, BB), 256, A3_BYTES>>>(pQ16, pK16, pV16, mask, pctx);

    // 4) output projection + residual (64-col tiles -> 256 CTAs)
    GemmArgs oa;
    oa.nseg = 1;
    oa.seg[0] = {pctx, pwo, bo, query, (void*)pX, 0, 0};
    oa.seg[1] = oa.seg[0];
    oa.seg[2] = oa.seg[0];
    gemm_f16<64><<<dim3(HH / 64, 16), 256>>>(oa);

    // 5) layernorm
    ln_kernel<<<BB * LQ, 256>>>(pX, ln_g, ln_b, out);
}